// round 3
// baseline (speedup 1.0000x reference)
#include <cuda_runtime.h>
#include <math.h>

#define NB 4
#define NP 8
#define NR 32
#define IMG 128
#define THW 1024
#define TCH 8
#define TGT 64
#define VMAX 1024
#define FMAX 1024

// Scratch (static device globals — no runtime allocation)
__device__ float4 g_tri[NR * FMAX * 6];            // 3.1 MB triangle setup
__device__ float4 g_rend[NR * IMG * IMG * 2];      // 16.8 MB rendered 8ch
__device__ float4 g_uvm[NR * IMG * IMG];           // 8.4 MB (u, v, mask, mask_rend)

// ---------------------------------------------------------------------------
// Kernel A: vertex transform + triangle setup, one block per render
// ---------------------------------------------------------------------------
__global__ __launch_bounds__(256) void setup_kernel(
    const float* __restrict__ vertices, const float* __restrict__ uv_map,
    const int* __restrict__ faces, const float* __restrict__ poses,
    int V, int F)
{
    __shared__ float4 s_vert[VMAX];   // px, py, z, iw
    __shared__ float  s_w[VMAX];
    __shared__ float  s_cp[16];
    int n = blockIdx.x;
    int b = n & (NB - 1);
    int p = n >> 2;
    int tid = threadIdx.x;

    if (tid == 0) {
        const float* ps = poses + (size_t)(b * NP + p) * 16;
        // cam_pose: R = gl @ poseR (negate rows 1,2), t = pose_t * (1,-1,-1)
        s_cp[0]  =  ps[0];  s_cp[1]  =  ps[1];  s_cp[2]  =  ps[2];  s_cp[3]  =  ps[3];
        s_cp[4]  = -ps[4];  s_cp[5]  = -ps[5];  s_cp[6]  = -ps[6];  s_cp[7]  = -ps[7];
        s_cp[8]  = -ps[8];  s_cp[9]  = -ps[9];  s_cp[10] = -ps[10]; s_cp[11] = -ps[11];
        s_cp[12] =  ps[12]; s_cp[13] =  ps[13]; s_cp[14] =  ps[14]; s_cp[15] =  ps[15];
    }
    __syncthreads();

    const double ncd = 0.1, fcd = 10.0;
    const float Qf  = (float)(-(fcd + ncd) / (fcd - ncd));
    const float QNf = (float)(-2.0 * (fcd * ncd) / (fcd - ncd));
    const float S = 1.875f;  // 2*120/128

    for (int v = tid; v < V; v += 256) {
        const float* vp = vertices + ((size_t)b * V + v) * 3;
        float X = vp[0], Y = vp[1], Z = vp[2];
        float c0 = ((X * s_cp[0]  + Y * s_cp[1])  + Z * s_cp[2])  + s_cp[3];
        float c1 = ((X * s_cp[4]  + Y * s_cp[5])  + Z * s_cp[6])  + s_cp[7];
        float c2 = ((X * s_cp[8]  + Y * s_cp[9])  + Z * s_cp[10]) + s_cp[11];
        float c3 = ((X * s_cp[12] + Y * s_cp[13]) + Z * s_cp[14]) + s_cp[15];
        float clx = c0 * S;
        float cly = c1 * S;
        float clz = c2 * Qf + c3 * QNf;
        float clw = -c2;
        float w = clw;
        float wsafe = (fabsf(w) < 1e-8f) ? 1e-8f : w;
        float ndx = clx / wsafe;
        float ndy = cly / wsafe;
        float ndz = clz / wsafe;
        float px = (ndx * 0.5f + 0.5f) * 128.0f;
        float py = (1.0f - (ndy * 0.5f + 0.5f)) * 128.0f;
        s_vert[v] = make_float4(px, py, ndz, 1.0f / wsafe);
        s_w[v] = w;
    }
    __syncthreads();

    for (int f = tid; f < F; f += 256) {
        const int* fp = faces + ((size_t)b * F + f) * 3;
        int i0 = fp[0], i1 = fp[1], i2 = fp[2];
        float4 A = s_vert[i0], Bv = s_vert[i1], C = s_vert[i2];
        bool front = (s_w[i0] > 1e-8f) && (s_w[i1] > 1e-8f) && (s_w[i2] > 1e-8f);
        float area = (Bv.x - A.x) * (C.y - A.y) - (Bv.y - A.y) * (C.x - A.x);
        bool valid = front && (fabsf(area) > 1e-9f);
        float a_safe = (fabsf(area) < 1e-9f) ? 1.0f : area;
        float inva = 1.0f / a_safe;
        const float* uvb = uv_map + (size_t)b * V * 2;
        float u0 = uvb[i0 * 2], vv0 = uvb[i0 * 2 + 1];
        float u1 = uvb[i1 * 2], vv1 = uvb[i1 * 2 + 1];
        float u2 = uvb[i2 * 2], vv2 = uvb[i2 * 2 + 1];
        float4* o = g_tri + ((size_t)n * FMAX + f) * 6;
        o[0] = make_float4(A.x, A.y, Bv.x, Bv.y);
        o[1] = make_float4(C.x, C.y, inva, A.z);
        o[2] = make_float4(Bv.z, C.z, A.w, Bv.w);
        o[3] = make_float4(C.w, A.w * u0, Bv.w * u1, C.w * u2);
        o[4] = make_float4(A.w * vv0, Bv.w * vv1, C.w * vv2, 0.0f);
        float bxmin, bymin, bxmax, bymax;
        if (valid) {
            bxmin = fminf(A.x, fminf(Bv.x, C.x)) - 0.5f;
            bxmax = fmaxf(A.x, fmaxf(Bv.x, C.x)) + 0.5f;
            bymin = fminf(A.y, fminf(Bv.y, C.y)) - 0.5f;
            bymax = fmaxf(A.y, fmaxf(Bv.y, C.y)) + 0.5f;
        } else {
            bxmin = 1e30f; bymin = 1e30f; bxmax = -1e30f; bymax = -1e30f;
        }
        o[5] = make_float4(bxmin, bymin, bxmax, bymax);
    }
}

// ---------------------------------------------------------------------------
// Kernel B: rasterize (per-pixel loop over triangles, scan-order depth test)
// then fused bilinear texture sampling.  Block = 128 cols x 8 rows.
// grid = (16 row-tiles, 32 renders)
// ---------------------------------------------------------------------------
__global__ __launch_bounds__(128) void raster_kernel(const float* __restrict__ texture, int F)
{
    __shared__ float4 s_tri[128 * 6];
    int n = blockIdx.y;
    int tile = blockIdx.x;
    int tid = threadIdx.x;            // column
    int r0 = tile * 8;
    float gx = tid + 0.5f;
    int warp = tid >> 5;
    float wxmin = warp * 32 + 0.5f;
    float wxmax = warp * 32 + 31.5f;
    float rymin = r0 + 0.5f;
    float rymax = r0 + 7.5f;

    float depth[8], uu[8], vv[8];
#pragma unroll
    for (int r = 0; r < 8; r++) { depth[r] = INFINITY; uu[r] = 0.f; vv[r] = 0.f; }

    const float4* tri = g_tri + (size_t)n * FMAX * 6;
    for (int base = 0; base < F; base += 128) {
        int cnt = min(128, F - base);
        __syncthreads();
        for (int i = tid; i < cnt * 6; i += 128) s_tri[i] = tri[base * 6 + i];
        __syncthreads();
        for (int t = 0; t < cnt; t++) {
            float4 bb = s_tri[t * 6 + 5];
            // warp-uniform bbox reject
            if (bb.x > wxmax || bb.z < wxmin || bb.y > rymax || bb.w < rymin) continue;
            float4 a0 = s_tri[t * 6 + 0];   // v0x v0y v1x v1y
            float4 a1 = s_tri[t * 6 + 1];   // v2x v2y inva z0
            float4 a2 = s_tri[t * 6 + 2];   // z1 z2 iw0 iw1
            float4 a3 = s_tri[t * 6 + 3];   // iw2 up0 up1 up2
            float4 a4 = s_tri[t * 6 + 4];   // vp0 vp1 vp2 -
            float d12x = a1.x - a0.z, d12y = a1.y - a0.w;   // v2 - v1
            float d20x = a0.x - a1.x, d20y = a0.y - a1.y;   // v0 - v2
            float d01x = a0.z - a0.x, d01y = a0.w - a0.y;   // v1 - v0
            float c0 = d12y * (gx - a0.z);
            float c1 = d20y * (gx - a1.x);
            float c2 = d01y * (gx - a0.x);
            float inva = a1.z;
#pragma unroll
            for (int r = 0; r < 8; r++) {
                float gy = r0 + r + 0.5f;
                float e0 = d12x * (gy - a0.w) - c0;
                float e1 = d20x * (gy - a1.y) - c1;
                float e2 = d01x * (gy - a0.y) - c2;
                float b0 = e0 * inva, b1 = e1 * inva, b2 = e2 * inva;
                if (b0 >= 0.f && b1 >= 0.f && b2 >= 0.f) {
                    float zp = b0 * a1.w + b1 * a2.x + b2 * a2.y;
                    if (zp < depth[r] && zp >= -1.f && zp <= 1.f) {
                        float pw = b0 * a2.z + b1 * a2.w + b2 * a3.x;
                        pw = (fabsf(pw) < 1e-12f) ? 1e-12f : pw;
                        depth[r] = zp;
                        uu[r] = (b0 * a3.y + b1 * a3.z + b2 * a3.w) / pw;
                        vv[r] = (b0 * a4.x + b1 * a4.y + b2 * a4.z) / pw;
                    }
                }
            }
        }
    }

    // Fused texture sampling + intermediate writes
    int bidx = n & (NB - 1);
    const float* tex = texture + (size_t)bidx * THW * THW * TCH;
#pragma unroll 1
    for (int r = 0; r < 8; r++) {
        int y = r0 + r;
        float u = uu[r], v = vv[r];
        float mask = (depth[r] < INFINITY) ? 1.0f : 0.0f;
        // reference: idx = clip(uv[...,::-1],0,1) * [th,tw]  (row from v, col from u)
        float idy = fminf(fmaxf(v, 0.f), 1.f) * 1024.0f;
        float idx = fminf(fmaxf(u, 0.f), 1.f) * 1024.0f;
        float fly = floorf(idy), flx = floorf(idx);
        float fy = idy - fly, fx = idx - flx;
        int i = (int)fly, j = (int)flx;
        int i0 = min(max(i, 0), 1023), j0 = min(max(j, 0), 1023);
        int i1 = min(i + 1, 1023),     j1 = min(j + 1, 1023);
        const float4* t00 = (const float4*)(tex + ((size_t)i0 * 1024 + j0) * 8);
        const float4* t01 = (const float4*)(tex + ((size_t)i0 * 1024 + j1) * 8);
        const float4* t10 = (const float4*)(tex + ((size_t)i1 * 1024 + j0) * 8);
        const float4* t11 = (const float4*)(tex + ((size_t)i1 * 1024 + j1) * 8);
        float w00 = (1.f - fx) * (1.f - fy);
        float w01 = fx * (1.f - fy);
        float w10 = (1.f - fx) * fy;
        float w11 = fx * fy;
        float4 qa00 = t00[0], qb00 = t00[1];
        float4 qa01 = t01[0], qb01 = t01[1];
        float4 qa10 = t10[0], qb10 = t10[1];
        float4 qa11 = t11[0], qb11 = t11[1];
        float4 oa, ob;
        oa.x = qa00.x * w00 + qa01.x * w01 + qa10.x * w10 + qa11.x * w11;
        oa.y = qa00.y * w00 + qa01.y * w01 + qa10.y * w10 + qa11.y * w11;
        oa.z = qa00.z * w00 + qa01.z * w01 + qa10.z * w10 + qa11.z * w11;
        oa.w = qa00.w * w00 + qa01.w * w01 + qa10.w * w10 + qa11.w * w11;
        ob.x = qb00.x * w00 + qb01.x * w01 + qb10.x * w10 + qb11.x * w11;
        ob.y = qb00.y * w00 + qb01.y * w01 + qb10.y * w10 + qb11.y * w11;
        ob.z = qb00.z * w00 + qb01.z * w01 + qb10.z * w10 + qb11.z * w11;
        ob.w = qb00.w * w00 + qb01.w * w01 + qb10.w * w10 + qb11.w * w11;
        size_t pix = (size_t)n * (IMG * IMG) + y * IMG + tid;
        g_rend[pix * 2 + 0] = oa;
        g_rend[pix * 2 + 1] = ob;
        g_uvm[pix] = make_float4(u, v, mask, ((u + v) > 0.f) ? 1.f : 0.f);
    }
}

// ---------------------------------------------------------------------------
// Kernel C: crop_and_resize (bilinear) + thresholds, one thread per out pixel
// ---------------------------------------------------------------------------
__global__ __launch_bounds__(256) void crop_kernel(const float* __restrict__ bboxes,
                                                   float* __restrict__ out)
{
    int gid = blockIdx.x * 256 + threadIdx.x;
    if (gid >= NR * TGT * TGT) return;
    int n = gid / (TGT * TGT);
    int pix = gid - n * (TGT * TGT);
    int ty = pix / TGT, tx = pix - (pix / TGT) * TGT;
    int b = n & 3, p = n >> 2;
    const float* bx = bboxes + (size_t)(b * NP + p) * 4;
    float y1 = bx[0], x1 = bx[1], y2 = bx[2], x2 = bx[3];
    float stepy = ((y2 - y1) * 127.0f) / 63.0f;
    float stepx = ((x2 - x1) * 127.0f) / 63.0f;
    float ys = y1 * 127.0f + (float)ty * stepy;
    float xs = x1 * 127.0f + (float)tx * stepx;
    bool vy = (ys >= 0.f) && (ys <= 127.f);
    bool vx = (xs >= 0.f) && (xs <= 127.f);
    bool valid = vy && vx;
    float yc = fminf(fmaxf(ys, 0.f), 127.f);
    float xc = fminf(fmaxf(xs, 0.f), 127.f);
    float y0f = floorf(yc), x0f = floorf(xc);
    float fy = yc - y0f, fx = xc - x0f;
    int i0 = (int)y0f, j0 = (int)x0f;
    int i1 = min(i0 + 1, 127), j1 = min(j0 + 1, 127);
    float w00 = (1.f - fy) * (1.f - fx);
    float w01 = (1.f - fy) * fx;
    float w10 = fy * (1.f - fx);
    float w11 = fy * fx;

    size_t ib = (size_t)n * (IMG * IMG);
    float4 m00 = g_uvm[ib + i0 * IMG + j0];
    float4 m01 = g_uvm[ib + i0 * IMG + j1];
    float4 m10 = g_uvm[ib + i1 * IMG + j0];
    float4 m11 = g_uvm[ib + i1 * IMG + j1];
    float4 ra00 = g_rend[(ib + i0 * IMG + j0) * 2],     rb00 = g_rend[(ib + i0 * IMG + j0) * 2 + 1];
    float4 ra01 = g_rend[(ib + i0 * IMG + j1) * 2],     rb01 = g_rend[(ib + i0 * IMG + j1) * 2 + 1];
    float4 ra10 = g_rend[(ib + i1 * IMG + j0) * 2],     rb10 = g_rend[(ib + i1 * IMG + j0) * 2 + 1];
    float4 ra11 = g_rend[(ib + i1 * IMG + j1) * 2],     rb11 = g_rend[(ib + i1 * IMG + j1) * 2 + 1];

    float mnew = m00.w * w00 + m01.w * w01 + m10.w * w10 + m11.w * w11;
    float mold = m00.z * w00 + m01.z * w01 + m10.z * w10 + m11.z * w11;
    float uo   = m00.x * w00 + m01.x * w01 + m10.x * w10 + m11.x * w11;
    float vo   = m00.y * w00 + m01.y * w01 + m10.y * w10 + m11.y * w11;
    float rc[8];
    rc[0] = ra00.x * w00 + ra01.x * w01 + ra10.x * w10 + ra11.x * w11;
    rc[1] = ra00.y * w00 + ra01.y * w01 + ra10.y * w10 + ra11.y * w11;
    rc[2] = ra00.z * w00 + ra01.z * w01 + ra10.z * w10 + ra11.z * w11;
    rc[3] = ra00.w * w00 + ra01.w * w01 + ra10.w * w10 + ra11.w * w11;
    rc[4] = rb00.x * w00 + rb01.x * w01 + rb10.x * w10 + rb11.x * w11;
    rc[5] = rb00.y * w00 + rb01.y * w01 + rb10.y * w10 + rb11.y * w11;
    rc[6] = rb00.z * w00 + rb01.z * w01 + rb10.z * w10 + rb11.z * w11;
    rc[7] = rb00.w * w00 + rb01.w * w01 + rb10.w * w10 + rb11.w * w11;

    float vscale = valid ? 1.0f : 0.0f;
    float4 o0, o1, o2;
    o0.x = (valid && mnew > 0.5f) ? 1.f : 0.f;
    o0.y = rc[0] * vscale;
    o0.z = rc[1] * vscale;
    o0.w = rc[2] * vscale;
    o1.x = rc[3] * vscale;
    o1.y = rc[4] * vscale;
    o1.z = rc[5] * vscale;
    o1.w = rc[6] * vscale;
    o2.x = rc[7] * vscale;
    o2.y = (valid && mold > 0.5f) ? 1.f : 0.f;
    o2.z = uo * vscale;
    o2.w = vo * vscale;
    float4* op = (float4*)(out + (size_t)gid * 12);
    op[0] = o0;
    op[1] = o1;
    op[2] = o2;
}

// ---------------------------------------------------------------------------
extern "C" void kernel_launch(void* const* d_in, const int* in_sizes, int n_in,
                              void* d_out, int out_size)
{
    const float* vertices = (const float*)d_in[0];
    const float* uv_map   = (const float*)d_in[1];
    const int*   faces    = (const int*)d_in[2];
    const float* texture  = (const float*)d_in[3];
    const float* poses    = (const float*)d_in[4];
    const float* bboxes   = (const float*)d_in[5];
    int V = in_sizes[0] / (NB * 3);
    int F = in_sizes[2] / (NB * 3);

    setup_kernel<<<NR, 256>>>(vertices, uv_map, faces, poses, V, F);
    dim3 gB(16, NR);
    raster_kernel<<<gB, 128>>>(texture, F);
    int npix = NR * TGT * TGT;
    crop_kernel<<<(npix + 255) / 256, 256>>>(bboxes, (float*)d_out);
}

// round 4
// speedup vs baseline: 2.1908x; 2.1908x over previous
#include <cuda_runtime.h>
#include <math.h>

#define NB 4
#define NP 8
#define NR 32
#define IMG 128
#define THW 1024
#define TCH 8
#define TGT 64
#define VMAX 1024
#define FMAX 1024

// Scratch (static device globals — no runtime allocation)
__device__ float4 g_trih[NR * FMAX * 5];           // hot: edges/bbox/z (6.5 MB)
__device__ float4 g_tric[NR * FMAX * 3];           // cold: ainv/iw/uw/vw (1.6 MB)
__device__ float4 g_rend[NR * IMG * IMG * 2];      // 16.8 MB rendered 8ch
__device__ float4 g_uvm[NR * IMG * IMG];           // 8.4 MB (u, v, mask, mask_rend)

// ---------------------------------------------------------------------------
// Kernel A: vertex transform + triangle setup, one block per render
// ---------------------------------------------------------------------------
__global__ __launch_bounds__(256) void setup_kernel(
    const float* __restrict__ vertices, const float* __restrict__ uv_map,
    const int* __restrict__ faces, const float* __restrict__ poses,
    int V, int F)
{
    __shared__ float4 s_vert[VMAX];   // px, py, z, iw
    __shared__ float  s_w[VMAX];
    __shared__ float  s_cp[16];
    int n = blockIdx.x;
    int b = n & (NB - 1);
    int p = n >> 2;
    int tid = threadIdx.x;

    if (tid == 0) {
        const float* ps = poses + (size_t)(b * NP + p) * 16;
        // cam_pose: R = gl @ poseR (negate rows 1,2), t = pose_t * (1,-1,-1)
        s_cp[0]  =  ps[0];  s_cp[1]  =  ps[1];  s_cp[2]  =  ps[2];  s_cp[3]  =  ps[3];
        s_cp[4]  = -ps[4];  s_cp[5]  = -ps[5];  s_cp[6]  = -ps[6];  s_cp[7]  = -ps[7];
        s_cp[8]  = -ps[8];  s_cp[9]  = -ps[9];  s_cp[10] = -ps[10]; s_cp[11] = -ps[11];
        s_cp[12] =  ps[12]; s_cp[13] =  ps[13]; s_cp[14] =  ps[14]; s_cp[15] =  ps[15];
    }
    __syncthreads();

    const double ncd = 0.1, fcd = 10.0;
    const float Qf  = (float)(-(fcd + ncd) / (fcd - ncd));
    const float QNf = (float)(-2.0 * (fcd * ncd) / (fcd - ncd));
    const float S = 1.875f;  // 2*120/128

    for (int v = tid; v < V; v += 256) {
        const float* vp = vertices + ((size_t)b * V + v) * 3;
        float X = vp[0], Y = vp[1], Z = vp[2];
        float c0 = ((X * s_cp[0]  + Y * s_cp[1])  + Z * s_cp[2])  + s_cp[3];
        float c1 = ((X * s_cp[4]  + Y * s_cp[5])  + Z * s_cp[6])  + s_cp[7];
        float c2 = ((X * s_cp[8]  + Y * s_cp[9])  + Z * s_cp[10]) + s_cp[11];
        float c3 = ((X * s_cp[12] + Y * s_cp[13]) + Z * s_cp[14]) + s_cp[15];
        float clx = c0 * S;
        float cly = c1 * S;
        float clz = c2 * Qf + c3 * QNf;
        float w = -c2;
        float wsafe = (fabsf(w) < 1e-8f) ? 1e-8f : w;
        float ndx = clx / wsafe;
        float ndy = cly / wsafe;
        float ndz = clz / wsafe;
        float px = (ndx * 0.5f + 0.5f) * 128.0f;
        float py = (1.0f - (ndy * 0.5f + 0.5f)) * 128.0f;
        s_vert[v] = make_float4(px, py, ndz, 1.0f / wsafe);
        s_w[v] = w;
    }
    __syncthreads();

    for (int f = tid; f < F; f += 256) {
        const int* fp = faces + ((size_t)b * F + f) * 3;
        int i0 = fp[0], i1 = fp[1], i2 = fp[2];
        float4 A = s_vert[i0], Bv = s_vert[i1], C = s_vert[i2];
        bool front = (s_w[i0] > 1e-8f) && (s_w[i1] > 1e-8f) && (s_w[i2] > 1e-8f);
        float area = (Bv.x - A.x) * (C.y - A.y) - (Bv.y - A.y) * (C.x - A.x);
        bool valid = front && (fabsf(area) > 1e-9f);
        float a_safe = (fabsf(area) < 1e-9f) ? 1.0f : area;
        float inva = 1.0f / a_safe;
        float s = (inva >= 0.0f) ? 1.0f : -1.0f;   // exact sign fold
        float ainv = fabsf(inva);
        // signed edge coefficients: e_i' = ex_i*(gy-ay_i) - ey_i*(gx-ax_i) = s*e_i
        float ex0 = s * (C.x - Bv.x),  ey0 = s * (C.y - Bv.y);   // edge(v1,v2), anchor v1
        float ex1 = s * (A.x - C.x),   ey1 = s * (A.y - C.y);    // edge(v2,v0), anchor v2
        float ex2 = s * (Bv.x - A.x),  ey2 = s * (Bv.y - A.y);   // edge(v0,v1), anchor v0
        float za = A.z * ainv, zb = Bv.z * ainv, zc = C.z * ainv;
        float dzp = ex0 * za + ex1 * zb + ex2 * zc;              // d(zp)/d(row)

        const float* uvb = uv_map + (size_t)b * V * 2;
        float u0 = uvb[i0 * 2], vv0 = uvb[i0 * 2 + 1];
        float u1 = uvb[i1 * 2], vv1 = uvb[i1 * 2 + 1];
        float u2 = uvb[i2 * 2], vv2 = uvb[i2 * 2 + 1];

        float bxmin, bymin, bxmax, bymax;
        if (valid) {
            bxmin = fminf(A.x, fminf(Bv.x, C.x)) - 0.5f;
            bxmax = fmaxf(A.x, fmaxf(Bv.x, C.x)) + 0.5f;
            bymin = fminf(A.y, fminf(Bv.y, C.y)) - 0.5f;
            bymax = fmaxf(A.y, fmaxf(Bv.y, C.y)) + 0.5f;
        } else {
            bxmin = 1e30f; bymin = 1e30f; bxmax = -1e30f; bymax = -1e30f;
        }
        float4* h = g_trih + ((size_t)n * FMAX + f) * 5;
        h[0] = make_float4(ex0, ey0, Bv.x, Bv.y);
        h[1] = make_float4(ex1, ey1, C.x, C.y);
        h[2] = make_float4(ex2, ey2, A.x, A.y);
        h[3] = make_float4(bxmin, bymin, bxmax, bymax);
        h[4] = make_float4(za, zb, zc, dzp);
        float4* c = g_tric + ((size_t)n * FMAX + f) * 3;
        c[0] = make_float4(ainv, A.w, Bv.w, C.w);
        c[1] = make_float4(A.w * u0, Bv.w * u1, C.w * u2, 0.0f);
        c[2] = make_float4(A.w * vv0, Bv.w * vv1, C.w * vv2, 0.0f);
    }
}

// ---------------------------------------------------------------------------
// Kernel B: rasterize with deferred shading.
// In-loop: incremental edges + zp, predicated (depth, win-index) update only.
// Post-loop: resolve winner attrs once per pixel, fused texture sampling.
// Block = 128 cols x 8 rows.  grid = (16 row-tiles, 32 renders)
// ---------------------------------------------------------------------------
__global__ __launch_bounds__(128) void raster_kernel(const float* __restrict__ texture, int F)
{
    __shared__ float4 s_tri[128 * 5];
    int n = blockIdx.y;
    int tile = blockIdx.x;
    int tid = threadIdx.x;            // column
    int r0 = tile * 8;
    float gx = tid + 0.5f;
    float gy0 = r0 + 0.5f;
    int warp = tid >> 5;
    float wxmin = warp * 32 + 0.5f;
    float wxmax = warp * 32 + 31.5f;
    float rymin = r0 + 0.5f;
    float rymax = r0 + 7.5f;

    float depth[8];
    int   win[8];
#pragma unroll
    for (int r = 0; r < 8; r++) { depth[r] = INFINITY; win[r] = -1; }

    const float4* trih = g_trih + (size_t)n * FMAX * 5;
    for (int base = 0; base < F; base += 128) {
        int cnt = min(128, F - base);
        __syncthreads();
        for (int i = tid; i < cnt * 5; i += 128) s_tri[i] = trih[base * 5 + i];
        __syncthreads();
        for (int t = 0; t < cnt; t++) {
            float4 bb = s_tri[t * 5 + 3];
            // warp-uniform bbox reject
            if (bb.x > wxmax || bb.z < wxmin || bb.y > rymax || bb.w < rymin) continue;
            float4 f0 = s_tri[t * 5 + 0];
            float4 f1 = s_tri[t * 5 + 1];
            float4 f2 = s_tri[t * 5 + 2];
            float4 f4 = s_tri[t * 5 + 4];
            // edges at (gx, gy0), anchored form (matches reference conditioning)
            float e0 = f0.x * (gy0 - f0.w) - f0.y * (gx - f0.z);
            float e1 = f1.x * (gy0 - f1.w) - f1.y * (gx - f1.z);
            float e2 = f2.x * (gy0 - f2.w) - f2.y * (gx - f2.z);
            float zp = e0 * f4.x + e1 * f4.y + e2 * f4.z;
            float dzp = f4.w;
            int tg = base + t;
#pragma unroll
            for (int r = 0; r < 8; r++) {
                bool upd = (e0 >= 0.f) && (e1 >= 0.f) && (e2 >= 0.f)
                         && (zp < depth[r]) && (fabsf(zp) <= 1.f);
                depth[r] = upd ? zp : depth[r];
                win[r]   = upd ? tg : win[r];
                e0 += f0.x; e1 += f1.x; e2 += f2.x; zp += dzp;
            }
        }
    }

    // Winner resolution + fused texture sampling + intermediate writes
    int bidx = n & (NB - 1);
    const float* tex = texture + (size_t)bidx * THW * THW * TCH;
    const float4* tric = g_tric + (size_t)n * FMAX * 3;
#pragma unroll 1
    for (int r = 0; r < 8; r++) {
        int y = r0 + r;
        float u = 0.f, v = 0.f;
        float mask = 0.f;
        int w = win[r];
        if (w >= 0) {
            mask = 1.f;
            float4 f0 = trih[w * 5 + 0];
            float4 f1 = trih[w * 5 + 1];
            float4 f2 = trih[w * 5 + 2];
            float4 c0 = tric[w * 3 + 0];
            float4 c1 = tric[w * 3 + 1];
            float4 c2 = tric[w * 3 + 2];
            float gy = y + 0.5f;
            float e0 = f0.x * (gy - f0.w) - f0.y * (gx - f0.z);
            float e1 = f1.x * (gy - f1.w) - f1.y * (gx - f1.z);
            float e2 = f2.x * (gy - f2.w) - f2.y * (gx - f2.z);
            float b0 = e0 * c0.x, b1 = e1 * c0.x, b2 = e2 * c0.x;
            float pw = b0 * c0.y + b1 * c0.z + b2 * c0.w;
            pw = (fabsf(pw) < 1e-12f) ? 1e-12f : pw;
            float ipw = 1.0f / pw;
            u = (b0 * c1.x + b1 * c1.y + b2 * c1.z) * ipw;
            v = (b0 * c2.x + b1 * c2.y + b2 * c2.z) * ipw;
        }
        // reference: idx = clip(uv[...,::-1],0,1) * [th,tw]  (row from v, col from u)
        float idy = fminf(fmaxf(v, 0.f), 1.f) * 1024.0f;
        float idx = fminf(fmaxf(u, 0.f), 1.f) * 1024.0f;
        float fly = floorf(idy), flx = floorf(idx);
        float fy = idy - fly, fx = idx - flx;
        int i = (int)fly, j = (int)flx;
        int i0 = min(max(i, 0), 1023), j0 = min(max(j, 0), 1023);
        int i1 = min(i + 1, 1023),     j1 = min(j + 1, 1023);
        const float4* t00 = (const float4*)(tex + ((size_t)i0 * 1024 + j0) * 8);
        const float4* t01 = (const float4*)(tex + ((size_t)i0 * 1024 + j1) * 8);
        const float4* t10 = (const float4*)(tex + ((size_t)i1 * 1024 + j0) * 8);
        const float4* t11 = (const float4*)(tex + ((size_t)i1 * 1024 + j1) * 8);
        float w00 = (1.f - fx) * (1.f - fy);
        float w01 = fx * (1.f - fy);
        float w10 = (1.f - fx) * fy;
        float w11 = fx * fy;
        float4 qa00 = t00[0], qb00 = t00[1];
        float4 qa01 = t01[0], qb01 = t01[1];
        float4 qa10 = t10[0], qb10 = t10[1];
        float4 qa11 = t11[0], qb11 = t11[1];
        float4 oa, ob;
        oa.x = qa00.x * w00 + qa01.x * w01 + qa10.x * w10 + qa11.x * w11;
        oa.y = qa00.y * w00 + qa01.y * w01 + qa10.y * w10 + qa11.y * w11;
        oa.z = qa00.z * w00 + qa01.z * w01 + qa10.z * w10 + qa11.z * w11;
        oa.w = qa00.w * w00 + qa01.w * w01 + qa10.w * w10 + qa11.w * w11;
        ob.x = qb00.x * w00 + qb01.x * w01 + qb10.x * w10 + qb11.x * w11;
        ob.y = qb00.y * w00 + qb01.y * w01 + qb10.y * w10 + qb11.y * w11;
        ob.z = qb00.z * w00 + qb01.z * w01 + qb10.z * w10 + qb11.z * w11;
        ob.w = qb00.w * w00 + qb01.w * w01 + qb10.w * w10 + qb11.w * w11;
        size_t pix = (size_t)n * (IMG * IMG) + y * IMG + tid;
        g_rend[pix * 2 + 0] = oa;
        g_rend[pix * 2 + 1] = ob;
        g_uvm[pix] = make_float4(u, v, mask, ((u + v) > 0.f) ? 1.f : 0.f);
    }
}

// ---------------------------------------------------------------------------
// Kernel C: crop_and_resize (bilinear) + thresholds, one thread per out pixel
// ---------------------------------------------------------------------------
__global__ __launch_bounds__(256) void crop_kernel(const float* __restrict__ bboxes,
                                                   float* __restrict__ out)
{
    int gid = blockIdx.x * 256 + threadIdx.x;
    if (gid >= NR * TGT * TGT) return;
    int n = gid / (TGT * TGT);
    int pix = gid - n * (TGT * TGT);
    int ty = pix / TGT, tx = pix - (pix / TGT) * TGT;
    int b = n & 3, p = n >> 2;
    const float* bx = bboxes + (size_t)(b * NP + p) * 4;
    float y1 = bx[0], x1 = bx[1], y2 = bx[2], x2 = bx[3];
    float stepy = ((y2 - y1) * 127.0f) / 63.0f;
    float stepx = ((x2 - x1) * 127.0f) / 63.0f;
    float ys = y1 * 127.0f + (float)ty * stepy;
    float xs = x1 * 127.0f + (float)tx * stepx;
    bool vy = (ys >= 0.f) && (ys <= 127.f);
    bool vx = (xs >= 0.f) && (xs <= 127.f);
    bool valid = vy && vx;
    float yc = fminf(fmaxf(ys, 0.f), 127.f);
    float xc = fminf(fmaxf(xs, 0.f), 127.f);
    float y0f = floorf(yc), x0f = floorf(xc);
    float fy = yc - y0f, fx = xc - x0f;
    int i0 = (int)y0f, j0 = (int)x0f;
    int i1 = min(i0 + 1, 127), j1 = min(j0 + 1, 127);
    float w00 = (1.f - fy) * (1.f - fx);
    float w01 = (1.f - fy) * fx;
    float w10 = fy * (1.f - fx);
    float w11 = fy * fx;

    size_t ib = (size_t)n * (IMG * IMG);
    float4 m00 = g_uvm[ib + i0 * IMG + j0];
    float4 m01 = g_uvm[ib + i0 * IMG + j1];
    float4 m10 = g_uvm[ib + i1 * IMG + j0];
    float4 m11 = g_uvm[ib + i1 * IMG + j1];
    float4 ra00 = g_rend[(ib + i0 * IMG + j0) * 2],     rb00 = g_rend[(ib + i0 * IMG + j0) * 2 + 1];
    float4 ra01 = g_rend[(ib + i0 * IMG + j1) * 2],     rb01 = g_rend[(ib + i0 * IMG + j1) * 2 + 1];
    float4 ra10 = g_rend[(ib + i1 * IMG + j0) * 2],     rb10 = g_rend[(ib + i1 * IMG + j0) * 2 + 1];
    float4 ra11 = g_rend[(ib + i1 * IMG + j1) * 2],     rb11 = g_rend[(ib + i1 * IMG + j1) * 2 + 1];

    float mnew = m00.w * w00 + m01.w * w01 + m10.w * w10 + m11.w * w11;
    float mold = m00.z * w00 + m01.z * w01 + m10.z * w10 + m11.z * w11;
    float uo   = m00.x * w00 + m01.x * w01 + m10.x * w10 + m11.x * w11;
    float vo   = m00.y * w00 + m01.y * w01 + m10.y * w10 + m11.y * w11;
    float rc[8];
    rc[0] = ra00.x * w00 + ra01.x * w01 + ra10.x * w10 + ra11.x * w11;
    rc[1] = ra00.y * w00 + ra01.y * w01 + ra10.y * w10 + ra11.y * w11;
    rc[2] = ra00.z * w00 + ra01.z * w01 + ra10.z * w10 + ra11.z * w11;
    rc[3] = ra00.w * w00 + ra01.w * w01 + ra10.w * w10 + ra11.w * w11;
    rc[4] = rb00.x * w00 + rb01.x * w01 + rb10.x * w10 + rb11.x * w11;
    rc[5] = rb00.y * w00 + rb01.y * w01 + rb10.y * w10 + rb11.y * w11;
    rc[6] = rb00.z * w00 + rb01.z * w01 + rb10.z * w10 + rb11.z * w11;
    rc[7] = rb00.w * w00 + rb01.w * w01 + rb10.w * w10 + rb11.w * w11;

    float vscale = valid ? 1.0f : 0.0f;
    float4 o0, o1, o2;
    o0.x = (valid && mnew > 0.5f) ? 1.f : 0.f;
    o0.y = rc[0] * vscale;
    o0.z = rc[1] * vscale;
    o0.w = rc[2] * vscale;
    o1.x = rc[3] * vscale;
    o1.y = rc[4] * vscale;
    o1.z = rc[5] * vscale;
    o1.w = rc[6] * vscale;
    o2.x = rc[7] * vscale;
    o2.y = (valid && mold > 0.5f) ? 1.f : 0.f;
    o2.z = uo * vscale;
    o2.w = vo * vscale;
    float4* op = (float4*)(out + (size_t)gid * 12);
    op[0] = o0;
    op[1] = o1;
    op[2] = o2;
}

// ---------------------------------------------------------------------------
extern "C" void kernel_launch(void* const* d_in, const int* in_sizes, int n_in,
                              void* d_out, int out_size)
{
    const float* vertices = (const float*)d_in[0];
    const float* uv_map   = (const float*)d_in[1];
    const int*   faces    = (const int*)d_in[2];
    const float* texture  = (const float*)d_in[3];
    const float* poses    = (const float*)d_in[4];
    const float* bboxes   = (const float*)d_in[5];
    int V = in_sizes[0] / (NB * 3);
    int F = in_sizes[2] / (NB * 3);

    setup_kernel<<<NR, 256>>>(vertices, uv_map, faces, poses, V, F);
    dim3 gB(16, NR);
    raster_kernel<<<gB, 128>>>(texture, F);
    int npix = NR * TGT * TGT;
    crop_kernel<<<(npix + 255) / 256, 256>>>(bboxes, (float*)d_out);
}

// round 5
// speedup vs baseline: 2.6228x; 1.1972x over previous
#include <cuda_runtime.h>
#include <math.h>

#define NB 4
#define NP 8
#define NR 32
#define IMG 128
#define THW 1024
#define TCH 8
#define TGT 64
#define VMAX 1024
#define FMAX 1024

// Scratch (static device globals — no runtime allocation)
__device__ float4 g_trih[NR * FMAX * 5];           // hot: edges/bbox/z (6.5 MB)
__device__ float4 g_tric[NR * FMAX * 3];           // cold: ainv/iw/uw/vw (1.6 MB)
__device__ float4 g_rend[NR * IMG * IMG * 2];      // 16.8 MB rendered 8ch
__device__ float4 g_uvm[NR * IMG * IMG];           // 8.4 MB (u, v, mask, mask_rend)

// ---------------------------------------------------------------------------
// Kernel A: vertex transform + triangle setup, one block per render
// ---------------------------------------------------------------------------
__global__ __launch_bounds__(256) void setup_kernel(
    const float* __restrict__ vertices, const float* __restrict__ uv_map,
    const int* __restrict__ faces, const float* __restrict__ poses,
    int V, int F)
{
    __shared__ float4 s_vert[VMAX];   // px, py, z, iw
    __shared__ float  s_w[VMAX];
    __shared__ float  s_cp[16];
    int n = blockIdx.x;
    int b = n & (NB - 1);
    int p = n >> 2;
    int tid = threadIdx.x;

    if (tid == 0) {
        const float* ps = poses + (size_t)(b * NP + p) * 16;
        // cam_pose: R = gl @ poseR (negate rows 1,2), t = pose_t * (1,-1,-1)
        s_cp[0]  =  ps[0];  s_cp[1]  =  ps[1];  s_cp[2]  =  ps[2];  s_cp[3]  =  ps[3];
        s_cp[4]  = -ps[4];  s_cp[5]  = -ps[5];  s_cp[6]  = -ps[6];  s_cp[7]  = -ps[7];
        s_cp[8]  = -ps[8];  s_cp[9]  = -ps[9];  s_cp[10] = -ps[10]; s_cp[11] = -ps[11];
        s_cp[12] =  ps[12]; s_cp[13] =  ps[13]; s_cp[14] =  ps[14]; s_cp[15] =  ps[15];
    }
    __syncthreads();

    const double ncd = 0.1, fcd = 10.0;
    const float Qf  = (float)(-(fcd + ncd) / (fcd - ncd));
    const float QNf = (float)(-2.0 * (fcd * ncd) / (fcd - ncd));
    const float S = 1.875f;  // 2*120/128

    for (int v = tid; v < V; v += 256) {
        const float* vp = vertices + ((size_t)b * V + v) * 3;
        float X = vp[0], Y = vp[1], Z = vp[2];
        float c0 = ((X * s_cp[0]  + Y * s_cp[1])  + Z * s_cp[2])  + s_cp[3];
        float c1 = ((X * s_cp[4]  + Y * s_cp[5])  + Z * s_cp[6])  + s_cp[7];
        float c2 = ((X * s_cp[8]  + Y * s_cp[9])  + Z * s_cp[10]) + s_cp[11];
        float c3 = ((X * s_cp[12] + Y * s_cp[13]) + Z * s_cp[14]) + s_cp[15];
        float clx = c0 * S;
        float cly = c1 * S;
        float clz = c2 * Qf + c3 * QNf;
        float w = -c2;
        float wsafe = (fabsf(w) < 1e-8f) ? 1e-8f : w;
        float ndx = clx / wsafe;
        float ndy = cly / wsafe;
        float ndz = clz / wsafe;
        float px = (ndx * 0.5f + 0.5f) * 128.0f;
        float py = (1.0f - (ndy * 0.5f + 0.5f)) * 128.0f;
        s_vert[v] = make_float4(px, py, ndz, 1.0f / wsafe);
        s_w[v] = w;
    }
    __syncthreads();

    for (int f = tid; f < F; f += 256) {
        const int* fp = faces + ((size_t)b * F + f) * 3;
        int i0 = fp[0], i1 = fp[1], i2 = fp[2];
        float4 A = s_vert[i0], Bv = s_vert[i1], C = s_vert[i2];
        bool front = (s_w[i0] > 1e-8f) && (s_w[i1] > 1e-8f) && (s_w[i2] > 1e-8f);
        float area = (Bv.x - A.x) * (C.y - A.y) - (Bv.y - A.y) * (C.x - A.x);
        bool valid = front && (fabsf(area) > 1e-9f);
        float a_safe = (fabsf(area) < 1e-9f) ? 1.0f : area;
        float inva = 1.0f / a_safe;
        float s = (inva >= 0.0f) ? 1.0f : -1.0f;   // exact sign fold
        float ainv = fabsf(inva);
        // signed edge coefficients: e_i' = ex_i*(gy-ay_i) - ey_i*(gx-ax_i) = s*e_i
        float ex0 = s * (C.x - Bv.x),  ey0 = s * (C.y - Bv.y);   // edge(v1,v2), anchor v1
        float ex1 = s * (A.x - C.x),   ey1 = s * (A.y - C.y);    // edge(v2,v0), anchor v2
        float ex2 = s * (Bv.x - A.x),  ey2 = s * (Bv.y - A.y);   // edge(v0,v1), anchor v0
        float za = A.z * ainv, zb = Bv.z * ainv, zc = C.z * ainv;
        float dzp = ex0 * za + ex1 * zb + ex2 * zc;              // d(zp)/d(row)

        const float* uvb = uv_map + (size_t)b * V * 2;
        float u0 = uvb[i0 * 2], vv0 = uvb[i0 * 2 + 1];
        float u1 = uvb[i1 * 2], vv1 = uvb[i1 * 2 + 1];
        float u2 = uvb[i2 * 2], vv2 = uvb[i2 * 2 + 1];

        float bxmin, bymin, bxmax, bymax;
        if (valid) {
            bxmin = fminf(A.x, fminf(Bv.x, C.x)) - 0.5f;
            bxmax = fmaxf(A.x, fmaxf(Bv.x, C.x)) + 0.5f;
            bymin = fminf(A.y, fminf(Bv.y, C.y)) - 0.5f;
            bymax = fmaxf(A.y, fmaxf(Bv.y, C.y)) + 0.5f;
        } else {
            bxmin = 1e30f; bymin = 1e30f; bxmax = -1e30f; bymax = -1e30f;
        }
        float4* h = g_trih + ((size_t)n * FMAX + f) * 5;
        h[0] = make_float4(ex0, ey0, Bv.x, Bv.y);
        h[1] = make_float4(ex1, ey1, C.x, C.y);
        h[2] = make_float4(ex2, ey2, A.x, A.y);
        h[3] = make_float4(bxmin, bymin, bxmax, bymax);
        h[4] = make_float4(za, zb, zc, dzp);
        float4* c = g_tric + ((size_t)n * FMAX + f) * 3;
        c[0] = make_float4(ainv, A.w, Bv.w, C.w);
        c[1] = make_float4(A.w * u0, Bv.w * u1, C.w * u2, 0.0f);
        c[2] = make_float4(A.w * vv0, Bv.w * vv1, C.w * vv2, 0.0f);
    }
}

// ---------------------------------------------------------------------------
// Kernel B: rasterize with deferred shading.
// Warp-ballot bbox compaction; per-row FFMA-from-anchor (no dependency chains);
// predicated (depth, win-index) update only.  Post-loop winner resolve +
// fused texture sampling.  Block = 128 cols x 8 rows. grid = (16, 32)
// ---------------------------------------------------------------------------
__global__ __launch_bounds__(128) void raster_kernel(const float* __restrict__ texture, int F)
{
    __shared__ float4 s_tri[128 * 5];
    int n = blockIdx.y;
    int tile = blockIdx.x;
    int tid = threadIdx.x;            // column
    int lane = tid & 31;
    int r0 = tile * 8;
    float gx = tid + 0.5f;
    float gy0 = r0 + 0.5f;
    int warp = tid >> 5;
    float wxmin = warp * 32 + 0.5f;
    float wxmax = warp * 32 + 31.5f;
    float rymin = r0 + 0.5f;
    float rymax = r0 + 7.5f;

    float depth[8];
    int   win[8];
#pragma unroll
    for (int r = 0; r < 8; r++) { depth[r] = INFINITY; win[r] = -1; }

    const float4* trih = g_trih + (size_t)n * FMAX * 5;
    for (int base = 0; base < F; base += 128) {
        int cnt = min(128, F - base);
        __syncthreads();
        for (int i = tid; i < cnt * 5; i += 128) s_tri[i] = trih[base * 5 + i];
        __syncthreads();
        for (int t0 = 0; t0 < cnt; t0 += 32) {
            // warp-cooperative bbox test: lane L tests triangle t0+L against
            // this warp's (uniform) tile rect, then ballot-compact.
            bool pass = false;
            int ti = t0 + lane;
            if (ti < cnt) {
                float4 bb = s_tri[ti * 5 + 3];
                pass = !(bb.x > wxmax || bb.z < wxmin || bb.y > rymax || bb.w < rymin);
            }
            unsigned mask = __ballot_sync(0xffffffffu, pass);
            while (mask) {
                int t = __ffs(mask) - 1;
                mask &= mask - 1;
                t += t0;
                float4 f0 = s_tri[t * 5 + 0];
                float4 f1 = s_tri[t * 5 + 1];
                float4 f2 = s_tri[t * 5 + 2];
                float4 f4 = s_tri[t * 5 + 4];
                // edges at (gx, gy0), anchored form
                float e0b = f0.x * (gy0 - f0.w) - f0.y * (gx - f0.z);
                float e1b = f1.x * (gy0 - f1.w) - f1.y * (gx - f1.z);
                float e2b = f2.x * (gy0 - f2.w) - f2.y * (gx - f2.z);
                float zpb = e0b * f4.x + e1b * f4.y + e2b * f4.z;
                float dzp = f4.w;
                int tg = base + t;
#pragma unroll
                for (int r = 0; r < 8; r++) {
                    float rf = (float)r;
                    float e0 = fmaf(rf, f0.x, e0b);
                    float e1 = fmaf(rf, f1.x, e1b);
                    float e2 = fmaf(rf, f2.x, e2b);
                    float zp = fmaf(rf, dzp, zpb);
                    float m  = fminf(fminf(e0, e1), e2);
                    bool upd = (m >= 0.f) && (zp < depth[r]) && (fabsf(zp) <= 1.f);
                    depth[r] = upd ? zp : depth[r];
                    win[r]   = upd ? tg : win[r];
                }
            }
        }
    }

    // Winner resolution + fused texture sampling + intermediate writes
    int bidx = n & (NB - 1);
    const float* tex = texture + (size_t)bidx * THW * THW * TCH;
    const float4* tric = g_tric + (size_t)n * FMAX * 3;
#pragma unroll 1
    for (int r = 0; r < 8; r++) {
        int y = r0 + r;
        float u = 0.f, v = 0.f;
        float mask = 0.f;
        int w = win[r];
        if (w >= 0) {
            mask = 1.f;
            float4 f0 = trih[w * 5 + 0];
            float4 f1 = trih[w * 5 + 1];
            float4 f2 = trih[w * 5 + 2];
            float4 c0 = tric[w * 3 + 0];
            float4 c1 = tric[w * 3 + 1];
            float4 c2 = tric[w * 3 + 2];
            float gy = y + 0.5f;
            float e0 = f0.x * (gy - f0.w) - f0.y * (gx - f0.z);
            float e1 = f1.x * (gy - f1.w) - f1.y * (gx - f1.z);
            float e2 = f2.x * (gy - f2.w) - f2.y * (gx - f2.z);
            float b0 = e0 * c0.x, b1 = e1 * c0.x, b2 = e2 * c0.x;
            float pw = b0 * c0.y + b1 * c0.z + b2 * c0.w;
            pw = (fabsf(pw) < 1e-12f) ? 1e-12f : pw;
            float ipw = 1.0f / pw;
            u = (b0 * c1.x + b1 * c1.y + b2 * c1.z) * ipw;
            v = (b0 * c2.x + b1 * c2.y + b2 * c2.z) * ipw;
        }
        // reference: idx = clip(uv[...,::-1],0,1) * [th,tw]  (row from v, col from u)
        float idy = fminf(fmaxf(v, 0.f), 1.f) * 1024.0f;
        float idx = fminf(fmaxf(u, 0.f), 1.f) * 1024.0f;
        float fly = floorf(idy), flx = floorf(idx);
        float fy = idy - fly, fx = idx - flx;
        int i = (int)fly, j = (int)flx;
        int i0 = min(max(i, 0), 1023), j0 = min(max(j, 0), 1023);
        int i1 = min(i + 1, 1023),     j1 = min(j + 1, 1023);
        const float4* t00 = (const float4*)(tex + ((size_t)i0 * 1024 + j0) * 8);
        const float4* t01 = (const float4*)(tex + ((size_t)i0 * 1024 + j1) * 8);
        const float4* t10 = (const float4*)(tex + ((size_t)i1 * 1024 + j0) * 8);
        const float4* t11 = (const float4*)(tex + ((size_t)i1 * 1024 + j1) * 8);
        float w00 = (1.f - fx) * (1.f - fy);
        float w01 = fx * (1.f - fy);
        float w10 = (1.f - fx) * fy;
        float w11 = fx * fy;
        float4 qa00 = t00[0], qb00 = t00[1];
        float4 qa01 = t01[0], qb01 = t01[1];
        float4 qa10 = t10[0], qb10 = t10[1];
        float4 qa11 = t11[0], qb11 = t11[1];
        float4 oa, ob;
        oa.x = qa00.x * w00 + qa01.x * w01 + qa10.x * w10 + qa11.x * w11;
        oa.y = qa00.y * w00 + qa01.y * w01 + qa10.y * w10 + qa11.y * w11;
        oa.z = qa00.z * w00 + qa01.z * w01 + qa10.z * w10 + qa11.z * w11;
        oa.w = qa00.w * w00 + qa01.w * w01 + qa10.w * w10 + qa11.w * w11;
        ob.x = qb00.x * w00 + qb01.x * w01 + qb10.x * w10 + qb11.x * w11;
        ob.y = qb00.y * w00 + qb01.y * w01 + qb10.y * w10 + qb11.y * w11;
        ob.z = qb00.z * w00 + qb01.z * w01 + qb10.z * w10 + qb11.z * w11;
        ob.w = qb00.w * w00 + qb01.w * w01 + qb10.w * w10 + qb11.w * w11;
        size_t pix = (size_t)n * (IMG * IMG) + y * IMG + tid;
        g_rend[pix * 2 + 0] = oa;
        g_rend[pix * 2 + 1] = ob;
        g_uvm[pix] = make_float4(u, v, mask, ((u + v) > 0.f) ? 1.f : 0.f);
    }
}

// ---------------------------------------------------------------------------
// Kernel C: crop_and_resize (bilinear) + thresholds, one thread per out pixel
// ---------------------------------------------------------------------------
__global__ __launch_bounds__(256) void crop_kernel(const float* __restrict__ bboxes,
                                                   float* __restrict__ out)
{
    int gid = blockIdx.x * 256 + threadIdx.x;
    if (gid >= NR * TGT * TGT) return;
    int n = gid / (TGT * TGT);
    int pix = gid - n * (TGT * TGT);
    int ty = pix / TGT, tx = pix - (pix / TGT) * TGT;
    int b = n & 3, p = n >> 2;
    const float* bx = bboxes + (size_t)(b * NP + p) * 4;
    float y1 = bx[0], x1 = bx[1], y2 = bx[2], x2 = bx[3];
    float stepy = ((y2 - y1) * 127.0f) / 63.0f;
    float stepx = ((x2 - x1) * 127.0f) / 63.0f;
    float ys = y1 * 127.0f + (float)ty * stepy;
    float xs = x1 * 127.0f + (float)tx * stepx;
    bool vy = (ys >= 0.f) && (ys <= 127.f);
    bool vx = (xs >= 0.f) && (xs <= 127.f);
    bool valid = vy && vx;
    float yc = fminf(fmaxf(ys, 0.f), 127.f);
    float xc = fminf(fmaxf(xs, 0.f), 127.f);
    float y0f = floorf(yc), x0f = floorf(xc);
    float fy = yc - y0f, fx = xc - x0f;
    int i0 = (int)y0f, j0 = (int)x0f;
    int i1 = min(i0 + 1, 127), j1 = min(j0 + 1, 127);
    float w00 = (1.f - fy) * (1.f - fx);
    float w01 = (1.f - fy) * fx;
    float w10 = fy * (1.f - fx);
    float w11 = fy * fx;

    size_t ib = (size_t)n * (IMG * IMG);
    float4 m00 = g_uvm[ib + i0 * IMG + j0];
    float4 m01 = g_uvm[ib + i0 * IMG + j1];
    float4 m10 = g_uvm[ib + i1 * IMG + j0];
    float4 m11 = g_uvm[ib + i1 * IMG + j1];
    float4 ra00 = g_rend[(ib + i0 * IMG + j0) * 2],     rb00 = g_rend[(ib + i0 * IMG + j0) * 2 + 1];
    float4 ra01 = g_rend[(ib + i0 * IMG + j1) * 2],     rb01 = g_rend[(ib + i0 * IMG + j1) * 2 + 1];
    float4 ra10 = g_rend[(ib + i1 * IMG + j0) * 2],     rb10 = g_rend[(ib + i1 * IMG + j0) * 2 + 1];
    float4 ra11 = g_rend[(ib + i1 * IMG + j1) * 2],     rb11 = g_rend[(ib + i1 * IMG + j1) * 2 + 1];

    float mnew = m00.w * w00 + m01.w * w01 + m10.w * w10 + m11.w * w11;
    float mold = m00.z * w00 + m01.z * w01 + m10.z * w10 + m11.z * w11;
    float uo   = m00.x * w00 + m01.x * w01 + m10.x * w10 + m11.x * w11;
    float vo   = m00.y * w00 + m01.y * w01 + m10.y * w10 + m11.y * w11;
    float rc[8];
    rc[0] = ra00.x * w00 + ra01.x * w01 + ra10.x * w10 + ra11.x * w11;
    rc[1] = ra00.y * w00 + ra01.y * w01 + ra10.y * w10 + ra11.y * w11;
    rc[2] = ra00.z * w00 + ra01.z * w01 + ra10.z * w10 + ra11.z * w11;
    rc[3] = ra00.w * w00 + ra01.w * w01 + ra10.w * w10 + ra11.w * w11;
    rc[4] = rb00.x * w00 + rb01.x * w01 + rb10.x * w10 + rb11.x * w11;
    rc[5] = rb00.y * w00 + rb01.y * w01 + rb10.y * w10 + rb11.y * w11;
    rc[6] = rb00.z * w00 + rb01.z * w01 + rb10.z * w10 + rb11.z * w11;
    rc[7] = rb00.w * w00 + rb01.w * w01 + rb10.w * w10 + rb11.w * w11;

    float vscale = valid ? 1.0f : 0.0f;
    float4 o0, o1, o2;
    o0.x = (valid && mnew > 0.5f) ? 1.f : 0.f;
    o0.y = rc[0] * vscale;
    o0.z = rc[1] * vscale;
    o0.w = rc[2] * vscale;
    o1.x = rc[3] * vscale;
    o1.y = rc[4] * vscale;
    o1.z = rc[5] * vscale;
    o1.w = rc[6] * vscale;
    o2.x = rc[7] * vscale;
    o2.y = (valid && mold > 0.5f) ? 1.f : 0.f;
    o2.z = uo * vscale;
    o2.w = vo * vscale;
    float4* op = (float4*)(out + (size_t)gid * 12);
    op[0] = o0;
    op[1] = o1;
    op[2] = o2;
}

// ---------------------------------------------------------------------------
extern "C" void kernel_launch(void* const* d_in, const int* in_sizes, int n_in,
                              void* d_out, int out_size)
{
    const float* vertices = (const float*)d_in[0];
    const float* uv_map   = (const float*)d_in[1];
    const int*   faces    = (const int*)d_in[2];
    const float* texture  = (const float*)d_in[3];
    const float* poses    = (const float*)d_in[4];
    const float* bboxes   = (const float*)d_in[5];
    int V = in_sizes[0] / (NB * 3);
    int F = in_sizes[2] / (NB * 3);

    setup_kernel<<<NR, 256>>>(vertices, uv_map, faces, poses, V, F);
    dim3 gB(16, NR);
    raster_kernel<<<gB, 128>>>(texture, F);
    int npix = NR * TGT * TGT;
    crop_kernel<<<(npix + 255) / 256, 256>>>(bboxes, (float*)d_out);
}

// round 6
// speedup vs baseline: 3.6377x; 1.3870x over previous
#include <cuda_runtime.h>
#include <math.h>

#define NB 4
#define NP 8
#define NR 32
#define IMG 128
#define THW 1024
#define TCH 8
#define TGT 64
#define VMAX 1024
#define FMAX 1024
#define NSPLIT 4

// Scratch (static device globals — no runtime allocation)
__device__ float4 g_trih[NR * FMAX * 5];           // hot: edges/bbox/z (6.5 MB)
__device__ float4 g_tric[NR * FMAX * 3];           // cold: ainv/iw/uw/vw (1.6 MB)
__device__ float2 g_part[NSPLIT * NR * IMG * IMG]; // 16.8 MB (depth, win) partials
__device__ float4 g_rend[NR * IMG * IMG * 2];      // 16.8 MB rendered 8ch
__device__ float4 g_uvm[NR * IMG * IMG];           // 8.4 MB (u, v, mask, mask_rend)

// ---------------------------------------------------------------------------
// Kernel A: vertex transform + triangle setup, one block per render
// ---------------------------------------------------------------------------
__global__ __launch_bounds__(256) void setup_kernel(
    const float* __restrict__ vertices, const float* __restrict__ uv_map,
    const int* __restrict__ faces, const float* __restrict__ poses,
    int V, int F)
{
    __shared__ float4 s_vert[VMAX];   // px, py, z, iw
    __shared__ float  s_w[VMAX];
    __shared__ float  s_cp[16];
    int n = blockIdx.x;
    int b = n & (NB - 1);
    int p = n >> 2;
    int tid = threadIdx.x;

    if (tid == 0) {
        const float* ps = poses + (size_t)(b * NP + p) * 16;
        // cam_pose: R = gl @ poseR (negate rows 1,2), t = pose_t * (1,-1,-1)
        s_cp[0]  =  ps[0];  s_cp[1]  =  ps[1];  s_cp[2]  =  ps[2];  s_cp[3]  =  ps[3];
        s_cp[4]  = -ps[4];  s_cp[5]  = -ps[5];  s_cp[6]  = -ps[6];  s_cp[7]  = -ps[7];
        s_cp[8]  = -ps[8];  s_cp[9]  = -ps[9];  s_cp[10] = -ps[10]; s_cp[11] = -ps[11];
        s_cp[12] =  ps[12]; s_cp[13] =  ps[13]; s_cp[14] =  ps[14]; s_cp[15] =  ps[15];
    }
    __syncthreads();

    const double ncd = 0.1, fcd = 10.0;
    const float Qf  = (float)(-(fcd + ncd) / (fcd - ncd));
    const float QNf = (float)(-2.0 * (fcd * ncd) / (fcd - ncd));
    const float S = 1.875f;  // 2*120/128

    for (int v = tid; v < V; v += 256) {
        const float* vp = vertices + ((size_t)b * V + v) * 3;
        float X = vp[0], Y = vp[1], Z = vp[2];
        float c0 = ((X * s_cp[0]  + Y * s_cp[1])  + Z * s_cp[2])  + s_cp[3];
        float c1 = ((X * s_cp[4]  + Y * s_cp[5])  + Z * s_cp[6])  + s_cp[7];
        float c2 = ((X * s_cp[8]  + Y * s_cp[9])  + Z * s_cp[10]) + s_cp[11];
        float c3 = ((X * s_cp[12] + Y * s_cp[13]) + Z * s_cp[14]) + s_cp[15];
        float clx = c0 * S;
        float cly = c1 * S;
        float clz = c2 * Qf + c3 * QNf;
        float w = -c2;
        float wsafe = (fabsf(w) < 1e-8f) ? 1e-8f : w;
        float ndx = clx / wsafe;
        float ndy = cly / wsafe;
        float ndz = clz / wsafe;
        float px = (ndx * 0.5f + 0.5f) * 128.0f;
        float py = (1.0f - (ndy * 0.5f + 0.5f)) * 128.0f;
        s_vert[v] = make_float4(px, py, ndz, 1.0f / wsafe);
        s_w[v] = w;
    }
    __syncthreads();

    for (int f = tid; f < F; f += 256) {
        const int* fp = faces + ((size_t)b * F + f) * 3;
        int i0 = fp[0], i1 = fp[1], i2 = fp[2];
        float4 A = s_vert[i0], Bv = s_vert[i1], C = s_vert[i2];
        bool front = (s_w[i0] > 1e-8f) && (s_w[i1] > 1e-8f) && (s_w[i2] > 1e-8f);
        float area = (Bv.x - A.x) * (C.y - A.y) - (Bv.y - A.y) * (C.x - A.x);
        bool valid = front && (fabsf(area) > 1e-9f);
        float a_safe = (fabsf(area) < 1e-9f) ? 1.0f : area;
        float inva = 1.0f / a_safe;
        float s = (inva >= 0.0f) ? 1.0f : -1.0f;   // exact sign fold
        float ainv = fabsf(inva);
        // signed edge coefficients: e_i' = ex_i*(gy-ay_i) - ey_i*(gx-ax_i) = s*e_i
        float ex0 = s * (C.x - Bv.x),  ey0 = s * (C.y - Bv.y);   // edge(v1,v2), anchor v1
        float ex1 = s * (A.x - C.x),   ey1 = s * (A.y - C.y);    // edge(v2,v0), anchor v2
        float ex2 = s * (Bv.x - A.x),  ey2 = s * (Bv.y - A.y);   // edge(v0,v1), anchor v0
        float za = A.z * ainv, zb = Bv.z * ainv, zc = C.z * ainv;
        float dzp = ex0 * za + ex1 * zb + ex2 * zc;              // d(zp)/d(row)

        const float* uvb = uv_map + (size_t)b * V * 2;
        float u0 = uvb[i0 * 2], vv0 = uvb[i0 * 2 + 1];
        float u1 = uvb[i1 * 2], vv1 = uvb[i1 * 2 + 1];
        float u2 = uvb[i2 * 2], vv2 = uvb[i2 * 2 + 1];

        float bxmin, bymin, bxmax, bymax;
        if (valid) {
            bxmin = fminf(A.x, fminf(Bv.x, C.x)) - 0.5f;
            bxmax = fmaxf(A.x, fmaxf(Bv.x, C.x)) + 0.5f;
            bymin = fminf(A.y, fminf(Bv.y, C.y)) - 0.5f;
            bymax = fmaxf(A.y, fmaxf(Bv.y, C.y)) + 0.5f;
        } else {
            bxmin = 1e30f; bymin = 1e30f; bxmax = -1e30f; bymax = -1e30f;
        }
        float4* h = g_trih + ((size_t)n * FMAX + f) * 5;
        h[0] = make_float4(ex0, ey0, Bv.x, Bv.y);
        h[1] = make_float4(ex1, ey1, C.x, C.y);
        h[2] = make_float4(ex2, ey2, A.x, A.y);
        h[3] = make_float4(bxmin, bymin, bxmax, bymax);
        h[4] = make_float4(za, zb, zc, dzp);
        float4* c = g_tric + ((size_t)n * FMAX + f) * 3;
        c[0] = make_float4(ainv, A.w, Bv.w, C.w);
        c[1] = make_float4(A.w * u0, Bv.w * u1, C.w * u2, 0.0f);
        c[2] = make_float4(A.w * vv0, Bv.w * vv1, C.w * vv2, 0.0f);
    }
}

// ---------------------------------------------------------------------------
// Kernel B: rasterize partials. Each block handles one (tile, render, split):
// scans triangles [F*s/4, F*(s+1)/4), produces per-pixel (depth, win) partial.
// Warp-ballot bbox compaction + per-row FFMA-from-anchor.
// Block = 128 cols x 8 rows. grid = (16, 32, 4)
// ---------------------------------------------------------------------------
__global__ __launch_bounds__(128) void raster_kernel(int F)
{
    __shared__ float4 s_tri[128 * 5];
    int n = blockIdx.y;
    int tile = blockIdx.x;
    int split = blockIdx.z;
    int tid = threadIdx.x;            // column
    int lane = tid & 31;
    int r0 = tile * 8;
    float gx = tid + 0.5f;
    float gy0 = r0 + 0.5f;
    int warp = tid >> 5;
    float wxmin = warp * 32 + 0.5f;
    float wxmax = warp * 32 + 31.5f;
    float rymin = r0 + 0.5f;
    float rymax = r0 + 7.5f;

    float depth[8];
    int   win[8];
#pragma unroll
    for (int r = 0; r < 8; r++) { depth[r] = INFINITY; win[r] = -1; }

    int fbeg = (F * split) / NSPLIT;
    int fend = (F * (split + 1)) / NSPLIT;

    const float4* trih = g_trih + (size_t)n * FMAX * 5;
    for (int base = fbeg; base < fend; base += 128) {
        int cnt = min(128, fend - base);
        __syncthreads();
        for (int i = tid; i < cnt * 5; i += 128) s_tri[i] = trih[(size_t)base * 5 + i];
        __syncthreads();
        for (int t0 = 0; t0 < cnt; t0 += 32) {
            // warp-cooperative bbox test: lane L tests triangle t0+L against
            // this warp's (uniform) tile rect, then ballot-compact.
            bool pass = false;
            int ti = t0 + lane;
            if (ti < cnt) {
                float4 bb = s_tri[ti * 5 + 3];
                pass = !(bb.x > wxmax || bb.z < wxmin || bb.y > rymax || bb.w < rymin);
            }
            unsigned mask = __ballot_sync(0xffffffffu, pass);
            while (mask) {
                int t = __ffs(mask) - 1;
                mask &= mask - 1;
                t += t0;
                float4 f0 = s_tri[t * 5 + 0];
                float4 f1 = s_tri[t * 5 + 1];
                float4 f2 = s_tri[t * 5 + 2];
                float4 f4 = s_tri[t * 5 + 4];
                // edges at (gx, gy0), anchored form
                float e0b = f0.x * (gy0 - f0.w) - f0.y * (gx - f0.z);
                float e1b = f1.x * (gy0 - f1.w) - f1.y * (gx - f1.z);
                float e2b = f2.x * (gy0 - f2.w) - f2.y * (gx - f2.z);
                float zpb = e0b * f4.x + e1b * f4.y + e2b * f4.z;
                float dzp = f4.w;
                int tg = base + t;
#pragma unroll
                for (int r = 0; r < 8; r++) {
                    float rf = (float)r;
                    float e0 = fmaf(rf, f0.x, e0b);
                    float e1 = fmaf(rf, f1.x, e1b);
                    float e2 = fmaf(rf, f2.x, e2b);
                    float zp = fmaf(rf, dzp, zpb);
                    float m  = fminf(fminf(e0, e1), e2);
                    bool upd = (m >= 0.f) && (zp < depth[r]) && (fabsf(zp) <= 1.f);
                    depth[r] = upd ? zp : depth[r];
                    win[r]   = upd ? tg : win[r];
                }
            }
        }
    }

    float2* part = g_part + ((size_t)split * NR + n) * (IMG * IMG);
#pragma unroll
    for (int r = 0; r < 8; r++) {
        int y = r0 + r;
        part[y * IMG + tid] = make_float2(depth[r], __int_as_float(win[r]));
    }
}

// ---------------------------------------------------------------------------
// Kernel B2: merge split partials, resolve winner attrs, texture sample.
// One thread per full-res pixel.
// ---------------------------------------------------------------------------
__global__ __launch_bounds__(256) void resolve_kernel(const float* __restrict__ texture)
{
    int gid = blockIdx.x * 256 + threadIdx.x;
    int n = gid >> 14;                 // / (IMG*IMG)
    int pix = gid & (IMG * IMG - 1);

    // merge partials: strict < keeps earliest split on exact depth ties,
    // matching sequential scan semantics (splits are index-ordered).
    const float2* part = g_part + (size_t)n * (IMG * IMG) + pix;
    float dmin = INFINITY;
    int w = -1;
#pragma unroll
    for (int s = 0; s < NSPLIT; s++) {
        float2 pr = part[(size_t)s * NR * IMG * IMG];
        if (pr.x < dmin) { dmin = pr.x; w = __float_as_int(pr.y); }
    }

    float gx = (pix & (IMG - 1)) + 0.5f;
    float gy = (pix >> 7) + 0.5f;
    float u = 0.f, v = 0.f;
    float mask = 0.f;
    if (w >= 0) {
        mask = 1.f;
        const float4* trih = g_trih + (size_t)n * FMAX * 5;
        const float4* tric = g_tric + (size_t)n * FMAX * 3;
        float4 f0 = trih[w * 5 + 0];
        float4 f1 = trih[w * 5 + 1];
        float4 f2 = trih[w * 5 + 2];
        float4 c0 = tric[w * 3 + 0];
        float4 c1 = tric[w * 3 + 1];
        float4 c2 = tric[w * 3 + 2];
        float e0 = f0.x * (gy - f0.w) - f0.y * (gx - f0.z);
        float e1 = f1.x * (gy - f1.w) - f1.y * (gx - f1.z);
        float e2 = f2.x * (gy - f2.w) - f2.y * (gx - f2.z);
        float b0 = e0 * c0.x, b1 = e1 * c0.x, b2 = e2 * c0.x;
        float pw = b0 * c0.y + b1 * c0.z + b2 * c0.w;
        pw = (fabsf(pw) < 1e-12f) ? 1e-12f : pw;
        float ipw = 1.0f / pw;
        u = (b0 * c1.x + b1 * c1.y + b2 * c1.z) * ipw;
        v = (b0 * c2.x + b1 * c2.y + b2 * c2.z) * ipw;
    }

    // reference: idx = clip(uv[...,::-1],0,1) * [th,tw]  (row from v, col from u)
    int bidx = n & (NB - 1);
    const float* tex = texture + (size_t)bidx * THW * THW * TCH;
    float idy = fminf(fmaxf(v, 0.f), 1.f) * 1024.0f;
    float idx = fminf(fmaxf(u, 0.f), 1.f) * 1024.0f;
    float fly = floorf(idy), flx = floorf(idx);
    float fy = idy - fly, fx = idx - flx;
    int i = (int)fly, j = (int)flx;
    int i0 = min(max(i, 0), 1023), j0 = min(max(j, 0), 1023);
    int i1 = min(i + 1, 1023),     j1 = min(j + 1, 1023);
    const float4* t00 = (const float4*)(tex + ((size_t)i0 * 1024 + j0) * 8);
    const float4* t01 = (const float4*)(tex + ((size_t)i0 * 1024 + j1) * 8);
    const float4* t10 = (const float4*)(tex + ((size_t)i1 * 1024 + j0) * 8);
    const float4* t11 = (const float4*)(tex + ((size_t)i1 * 1024 + j1) * 8);
    float w00 = (1.f - fx) * (1.f - fy);
    float w01 = fx * (1.f - fy);
    float w10 = (1.f - fx) * fy;
    float w11 = fx * fy;
    float4 qa00 = t00[0], qb00 = t00[1];
    float4 qa01 = t01[0], qb01 = t01[1];
    float4 qa10 = t10[0], qb10 = t10[1];
    float4 qa11 = t11[0], qb11 = t11[1];
    float4 oa, ob;
    oa.x = qa00.x * w00 + qa01.x * w01 + qa10.x * w10 + qa11.x * w11;
    oa.y = qa00.y * w00 + qa01.y * w01 + qa10.y * w10 + qa11.y * w11;
    oa.z = qa00.z * w00 + qa01.z * w01 + qa10.z * w10 + qa11.z * w11;
    oa.w = qa00.w * w00 + qa01.w * w01 + qa10.w * w10 + qa11.w * w11;
    ob.x = qb00.x * w00 + qb01.x * w01 + qb10.x * w10 + qb11.x * w11;
    ob.y = qb00.y * w00 + qb01.y * w01 + qb10.y * w10 + qb11.y * w11;
    ob.z = qb00.z * w00 + qb01.z * w01 + qb10.z * w10 + qb11.z * w11;
    ob.w = qb00.w * w00 + qb01.w * w01 + qb10.w * w10 + qb11.w * w11;
    g_rend[(size_t)gid * 2 + 0] = oa;
    g_rend[(size_t)gid * 2 + 1] = ob;
    g_uvm[gid] = make_float4(u, v, mask, ((u + v) > 0.f) ? 1.f : 0.f);
}

// ---------------------------------------------------------------------------
// Kernel C: crop_and_resize (bilinear) + thresholds, one thread per out pixel
// ---------------------------------------------------------------------------
__global__ __launch_bounds__(256) void crop_kernel(const float* __restrict__ bboxes,
                                                   float* __restrict__ out)
{
    int gid = blockIdx.x * 256 + threadIdx.x;
    if (gid >= NR * TGT * TGT) return;
    int n = gid / (TGT * TGT);
    int pix = gid - n * (TGT * TGT);
    int ty = pix / TGT, tx = pix - (pix / TGT) * TGT;
    int b = n & 3, p = n >> 2;
    const float* bx = bboxes + (size_t)(b * NP + p) * 4;
    float y1 = bx[0], x1 = bx[1], y2 = bx[2], x2 = bx[3];
    float stepy = ((y2 - y1) * 127.0f) / 63.0f;
    float stepx = ((x2 - x1) * 127.0f) / 63.0f;
    float ys = y1 * 127.0f + (float)ty * stepy;
    float xs = x1 * 127.0f + (float)tx * stepx;
    bool vy = (ys >= 0.f) && (ys <= 127.f);
    bool vx = (xs >= 0.f) && (xs <= 127.f);
    bool valid = vy && vx;
    float yc = fminf(fmaxf(ys, 0.f), 127.f);
    float xc = fminf(fmaxf(xs, 0.f), 127.f);
    float y0f = floorf(yc), x0f = floorf(xc);
    float fy = yc - y0f, fx = xc - x0f;
    int i0 = (int)y0f, j0 = (int)x0f;
    int i1 = min(i0 + 1, 127), j1 = min(j0 + 1, 127);
    float w00 = (1.f - fy) * (1.f - fx);
    float w01 = (1.f - fy) * fx;
    float w10 = fy * (1.f - fx);
    float w11 = fy * fx;

    size_t ib = (size_t)n * (IMG * IMG);
    float4 m00 = g_uvm[ib + i0 * IMG + j0];
    float4 m01 = g_uvm[ib + i0 * IMG + j1];
    float4 m10 = g_uvm[ib + i1 * IMG + j0];
    float4 m11 = g_uvm[ib + i1 * IMG + j1];
    float4 ra00 = g_rend[(ib + i0 * IMG + j0) * 2],     rb00 = g_rend[(ib + i0 * IMG + j0) * 2 + 1];
    float4 ra01 = g_rend[(ib + i0 * IMG + j1) * 2],     rb01 = g_rend[(ib + i0 * IMG + j1) * 2 + 1];
    float4 ra10 = g_rend[(ib + i1 * IMG + j0) * 2],     rb10 = g_rend[(ib + i1 * IMG + j0) * 2 + 1];
    float4 ra11 = g_rend[(ib + i1 * IMG + j1) * 2],     rb11 = g_rend[(ib + i1 * IMG + j1) * 2 + 1];

    float mnew = m00.w * w00 + m01.w * w01 + m10.w * w10 + m11.w * w11;
    float mold = m00.z * w00 + m01.z * w01 + m10.z * w10 + m11.z * w11;
    float uo   = m00.x * w00 + m01.x * w01 + m10.x * w10 + m11.x * w11;
    float vo   = m00.y * w00 + m01.y * w01 + m10.y * w10 + m11.y * w11;
    float rc[8];
    rc[0] = ra00.x * w00 + ra01.x * w01 + ra10.x * w10 + ra11.x * w11;
    rc[1] = ra00.y * w00 + ra01.y * w01 + ra10.y * w10 + ra11.y * w11;
    rc[2] = ra00.z * w00 + ra01.z * w01 + ra10.z * w10 + ra11.z * w11;
    rc[3] = ra00.w * w00 + ra01.w * w01 + ra10.w * w10 + ra11.w * w11;
    rc[4] = rb00.x * w00 + rb01.x * w01 + rb10.x * w10 + rb11.x * w11;
    rc[5] = rb00.y * w00 + rb01.y * w01 + rb10.y * w10 + rb11.y * w11;
    rc[6] = rb00.z * w00 + rb01.z * w01 + rb10.z * w10 + rb11.z * w11;
    rc[7] = rb00.w * w00 + rb01.w * w01 + rb10.w * w10 + rb11.w * w11;

    float vscale = valid ? 1.0f : 0.0f;
    float4 o0, o1, o2;
    o0.x = (valid && mnew > 0.5f) ? 1.f : 0.f;
    o0.y = rc[0] * vscale;
    o0.z = rc[1] * vscale;
    o0.w = rc[2] * vscale;
    o1.x = rc[3] * vscale;
    o1.y = rc[4] * vscale;
    o1.z = rc[5] * vscale;
    o1.w = rc[6] * vscale;
    o2.x = rc[7] * vscale;
    o2.y = (valid && mold > 0.5f) ? 1.f : 0.f;
    o2.z = uo * vscale;
    o2.w = vo * vscale;
    float4* op = (float4*)(out + (size_t)gid * 12);
    op[0] = o0;
    op[1] = o1;
    op[2] = o2;
}

// ---------------------------------------------------------------------------
extern "C" void kernel_launch(void* const* d_in, const int* in_sizes, int n_in,
                              void* d_out, int out_size)
{
    const float* vertices = (const float*)d_in[0];
    const float* uv_map   = (const float*)d_in[1];
    const int*   faces    = (const int*)d_in[2];
    const float* texture  = (const float*)d_in[3];
    const float* poses    = (const float*)d_in[4];
    const float* bboxes   = (const float*)d_in[5];
    int V = in_sizes[0] / (NB * 3);
    int F = in_sizes[2] / (NB * 3);

    setup_kernel<<<NR, 256>>>(vertices, uv_map, faces, poses, V, F);
    dim3 gB(16, NR, NSPLIT);
    raster_kernel<<<gB, 128>>>(F);
    int nfull = NR * IMG * IMG;
    resolve_kernel<<<nfull / 256, 256>>>(texture);
    int npix = NR * TGT * TGT;
    crop_kernel<<<(npix + 255) / 256, 256>>>(bboxes, (float*)d_out);
}

// round 7
// speedup vs baseline: 4.9748x; 1.3676x over previous
#include <cuda_runtime.h>
#include <math.h>

#define NB 4
#define NP 8
#define NR 32
#define IMG 128
#define THW 1024
#define TCH 8
#define TGT 64
#define VMAX 1024
#define FMAX 1024
#define NSPLIT 4

// Scratch (static device globals — no runtime allocation)
__device__ float4 g_trih[NR * FMAX * 5];           // hot: edges/bbox/z (6.5 MB)
__device__ float4 g_tric[NR * FMAX * 3];           // cold: ainv/iw/uw/vw (1.6 MB)
__device__ float2 g_part[NSPLIT * NR * IMG * IMG]; // 16.8 MB (depth, win) partials
__device__ float4 g_rend[NR * IMG * IMG * 2];      // 16.8 MB rendered 8ch
__device__ float4 g_uvm[NR * IMG * IMG];           // 8.4 MB (u, v, mask, mask_rend)
__device__ int4   g_rect[NR];                      // live pixel rect per render

// ---------------------------------------------------------------------------
// Kernel A: vertex transform + triangle setup + live-rect, one block per render
// ---------------------------------------------------------------------------
__global__ __launch_bounds__(256) void setup_kernel(
    const float* __restrict__ vertices, const float* __restrict__ uv_map,
    const int* __restrict__ faces, const float* __restrict__ poses,
    const float* __restrict__ bboxes, int V, int F)
{
    __shared__ float4 s_vert[VMAX];   // px, py, z, iw
    __shared__ float  s_w[VMAX];
    __shared__ float  s_cp[16];
    int n = blockIdx.x;
    int b = n & (NB - 1);
    int p = n >> 2;
    int tid = threadIdx.x;

    if (tid == 0) {
        const float* ps = poses + (size_t)(b * NP + p) * 16;
        // cam_pose: R = gl @ poseR (negate rows 1,2), t = pose_t * (1,-1,-1)
        s_cp[0]  =  ps[0];  s_cp[1]  =  ps[1];  s_cp[2]  =  ps[2];  s_cp[3]  =  ps[3];
        s_cp[4]  = -ps[4];  s_cp[5]  = -ps[5];  s_cp[6]  = -ps[6];  s_cp[7]  = -ps[7];
        s_cp[8]  = -ps[8];  s_cp[9]  = -ps[9];  s_cp[10] = -ps[10]; s_cp[11] = -ps[11];
        s_cp[12] =  ps[12]; s_cp[13] =  ps[13]; s_cp[14] =  ps[14]; s_cp[15] =  ps[15];
    }
    if (tid == 32) {
        // live rect: pixels crop can validly sample (padded ±1 vs ulp drift)
        const float* bx = bboxes + (size_t)(b * NP + p) * 4;
        float y1 = bx[0], x1 = bx[1], y2 = bx[2], x2 = bx[3];
        int ry0 = max(0, (int)floorf(fmaxf(0.f, y1 * 127.f)) - 1);
        int ry1 = min(127, (int)floorf(fminf(127.f, y2 * 127.f)) + 2);
        int rx0 = max(0, (int)floorf(fmaxf(0.f, x1 * 127.f)) - 1);
        int rx1 = min(127, (int)floorf(fminf(127.f, x2 * 127.f)) + 2);
        g_rect[n] = make_int4(rx0, ry0, rx1, ry1);
    }
    __syncthreads();

    const double ncd = 0.1, fcd = 10.0;
    const float Qf  = (float)(-(fcd + ncd) / (fcd - ncd));
    const float QNf = (float)(-2.0 * (fcd * ncd) / (fcd - ncd));
    const float S = 1.875f;  // 2*120/128

    for (int v = tid; v < V; v += 256) {
        const float* vp = vertices + ((size_t)b * V + v) * 3;
        float X = vp[0], Y = vp[1], Z = vp[2];
        float c0 = ((X * s_cp[0]  + Y * s_cp[1])  + Z * s_cp[2])  + s_cp[3];
        float c1 = ((X * s_cp[4]  + Y * s_cp[5])  + Z * s_cp[6])  + s_cp[7];
        float c2 = ((X * s_cp[8]  + Y * s_cp[9])  + Z * s_cp[10]) + s_cp[11];
        float c3 = ((X * s_cp[12] + Y * s_cp[13]) + Z * s_cp[14]) + s_cp[15];
        float clx = c0 * S;
        float cly = c1 * S;
        float clz = c2 * Qf + c3 * QNf;
        float w = -c2;
        float wsafe = (fabsf(w) < 1e-8f) ? 1e-8f : w;
        float ndx = clx / wsafe;
        float ndy = cly / wsafe;
        float ndz = clz / wsafe;
        float px = (ndx * 0.5f + 0.5f) * 128.0f;
        float py = (1.0f - (ndy * 0.5f + 0.5f)) * 128.0f;
        s_vert[v] = make_float4(px, py, ndz, 1.0f / wsafe);
        s_w[v] = w;
    }
    __syncthreads();

    for (int f = tid; f < F; f += 256) {
        const int* fp = faces + ((size_t)b * F + f) * 3;
        int i0 = fp[0], i1 = fp[1], i2 = fp[2];
        float4 A = s_vert[i0], Bv = s_vert[i1], C = s_vert[i2];
        bool front = (s_w[i0] > 1e-8f) && (s_w[i1] > 1e-8f) && (s_w[i2] > 1e-8f);
        float area = (Bv.x - A.x) * (C.y - A.y) - (Bv.y - A.y) * (C.x - A.x);
        bool valid = front && (fabsf(area) > 1e-9f);
        float a_safe = (fabsf(area) < 1e-9f) ? 1.0f : area;
        float inva = 1.0f / a_safe;
        float s = (inva >= 0.0f) ? 1.0f : -1.0f;   // exact sign fold
        float ainv = fabsf(inva);
        // signed edge coefficients: e_i' = ex_i*(gy-ay_i) - ey_i*(gx-ax_i) = s*e_i
        float ex0 = s * (C.x - Bv.x),  ey0 = s * (C.y - Bv.y);   // edge(v1,v2), anchor v1
        float ex1 = s * (A.x - C.x),   ey1 = s * (A.y - C.y);    // edge(v2,v0), anchor v2
        float ex2 = s * (Bv.x - A.x),  ey2 = s * (Bv.y - A.y);   // edge(v0,v1), anchor v0
        float za = A.z * ainv, zb = Bv.z * ainv, zc = C.z * ainv;
        float dzp = ex0 * za + ex1 * zb + ex2 * zc;              // d(zp)/d(row)

        const float* uvb = uv_map + (size_t)b * V * 2;
        float u0 = uvb[i0 * 2], vv0 = uvb[i0 * 2 + 1];
        float u1 = uvb[i1 * 2], vv1 = uvb[i1 * 2 + 1];
        float u2 = uvb[i2 * 2], vv2 = uvb[i2 * 2 + 1];

        float bxmin, bymin, bxmax, bymax;
        if (valid) {
            bxmin = fminf(A.x, fminf(Bv.x, C.x)) - 0.5f;
            bxmax = fmaxf(A.x, fmaxf(Bv.x, C.x)) + 0.5f;
            bymin = fminf(A.y, fminf(Bv.y, C.y)) - 0.5f;
            bymax = fmaxf(A.y, fmaxf(Bv.y, C.y)) + 0.5f;
        } else {
            bxmin = 1e30f; bymin = 1e30f; bxmax = -1e30f; bymax = -1e30f;
        }
        float4* h = g_trih + ((size_t)n * FMAX + f) * 5;
        h[0] = make_float4(ex0, ey0, Bv.x, Bv.y);
        h[1] = make_float4(ex1, ey1, C.x, C.y);
        h[2] = make_float4(ex2, ey2, A.x, A.y);
        h[3] = make_float4(bxmin, bymin, bxmax, bymax);
        h[4] = make_float4(za, zb, zc, dzp);
        float4* c = g_tric + ((size_t)n * FMAX + f) * 3;
        c[0] = make_float4(ainv, A.w, Bv.w, C.w);
        c[1] = make_float4(A.w * u0, Bv.w * u1, C.w * u2, 0.0f);
        c[2] = make_float4(A.w * vv0, Bv.w * vv1, C.w * vv2, 0.0f);
    }
}

// ---------------------------------------------------------------------------
// Kernel B: rasterize partials, restricted to the live rect.
// Row-strips outside the rect exit immediately; warp rects are clamped to the
// rect (tighter bbox reject); exact edge-corner reject in the ballot phase.
// Block = 128 cols x 8 rows. grid = (16, 32, NSPLIT)
// ---------------------------------------------------------------------------
__global__ __launch_bounds__(128) void raster_kernel(int F)
{
    __shared__ float4 s_tri[128 * 5];
    int n = blockIdx.y;
    int tile = blockIdx.x;
    int split = blockIdx.z;
    int r0 = tile * 8;
    int4 rect = g_rect[n];
    if (r0 > rect.w || r0 + 7 < rect.y) return;   // whole strip dead (uniform)

    int tid = threadIdx.x;            // column
    int lane = tid & 31;
    float gx = tid + 0.5f;
    float gy0 = r0 + 0.5f;
    int warp = tid >> 5;
    // warp rect clamped to live rect (warp-uniform)
    float wxmin = fmaxf(warp * 32 + 0.5f, rect.x + 0.5f);
    float wxmax = fminf(warp * 32 + 31.5f, rect.z + 0.5f);
    float rymin = fmaxf(r0 + 0.5f, rect.y + 0.5f);
    float rymax = fminf(r0 + 7.5f, rect.w + 0.5f);
    bool warp_live = (wxmin <= wxmax);

    float depth[8];
    int   win[8];
#pragma unroll
    for (int r = 0; r < 8; r++) { depth[r] = INFINITY; win[r] = -1; }

    int fbeg = (F * split) / NSPLIT;
    int fend = (F * (split + 1)) / NSPLIT;

    const float4* trih = g_trih + (size_t)n * FMAX * 5;
    for (int base = fbeg; base < fend; base += 128) {
        int cnt = min(128, fend - base);
        __syncthreads();
        for (int i = tid; i < cnt * 5; i += 128) s_tri[i] = trih[(size_t)base * 5 + i];
        __syncthreads();
        for (int t0 = 0; t0 < cnt; t0 += 32) {
            // lane L tests triangle t0+L: bbox vs warp rect, then exact
            // edge-corner reject (max of each linear edge over the rect).
            bool pass = false;
            int ti = t0 + lane;
            if (warp_live && ti < cnt) {
                float4 bb = s_tri[ti * 5 + 3];
                pass = !(bb.x > wxmax || bb.z < wxmin || bb.y > rymax || bb.w < rymin);
                if (pass) {
                    float4 t0v = s_tri[ti * 5 + 0];
                    float4 t1v = s_tri[ti * 5 + 1];
                    float4 t2v = s_tri[ti * 5 + 2];
                    // e = ex*(y-ay) - ey*(x-ax); max at y*=(ex>=0?ymax:ymin),
                    // x*=(ey>=0?xmin:xmax)
                    float y0s = (t0v.x >= 0.f) ? rymax : rymin;
                    float x0s = (t0v.y >= 0.f) ? wxmin : wxmax;
                    float em0 = t0v.x * (y0s - t0v.w) - t0v.y * (x0s - t0v.z);
                    float y1s = (t1v.x >= 0.f) ? rymax : rymin;
                    float x1s = (t1v.y >= 0.f) ? wxmin : wxmax;
                    float em1 = t1v.x * (y1s - t1v.w) - t1v.y * (x1s - t1v.z);
                    float y2s = (t2v.x >= 0.f) ? rymax : rymin;
                    float x2s = (t2v.y >= 0.f) ? wxmin : wxmax;
                    float em2 = t2v.x * (y2s - t2v.w) - t2v.y * (x2s - t2v.z);
                    pass = (em0 >= 0.f) && (em1 >= 0.f) && (em2 >= 0.f);
                }
            }
            unsigned mask = __ballot_sync(0xffffffffu, pass);
            while (mask) {
                int t = __ffs(mask) - 1;
                mask &= mask - 1;
                t += t0;
                float4 f0 = s_tri[t * 5 + 0];
                float4 f1 = s_tri[t * 5 + 1];
                float4 f2 = s_tri[t * 5 + 2];
                float4 f4 = s_tri[t * 5 + 4];
                // edges at (gx, gy0), anchored form
                float e0b = f0.x * (gy0 - f0.w) - f0.y * (gx - f0.z);
                float e1b = f1.x * (gy0 - f1.w) - f1.y * (gx - f1.z);
                float e2b = f2.x * (gy0 - f2.w) - f2.y * (gx - f2.z);
                float zpb = e0b * f4.x + e1b * f4.y + e2b * f4.z;
                float dzp = f4.w;
                int tg = base + t;
#pragma unroll
                for (int r = 0; r < 8; r++) {
                    float rf = (float)r;
                    float e0 = fmaf(rf, f0.x, e0b);
                    float e1 = fmaf(rf, f1.x, e1b);
                    float e2 = fmaf(rf, f2.x, e2b);
                    float zp = fmaf(rf, dzp, zpb);
                    float m  = fminf(fminf(e0, e1), e2);
                    bool upd = (m >= 0.f) && (zp < depth[r]) && (fabsf(zp) <= 1.f);
                    depth[r] = upd ? zp : depth[r];
                    win[r]   = upd ? tg : win[r];
                }
            }
        }
    }

    float2* part = g_part + ((size_t)split * NR + n) * (IMG * IMG);
#pragma unroll
    for (int r = 0; r < 8; r++) {
        int y = r0 + r;
        part[y * IMG + tid] = make_float2(depth[r], __int_as_float(win[r]));
    }
}

// ---------------------------------------------------------------------------
// Kernel B2: merge split partials, resolve winner attrs, texture sample.
// Skips pixels outside the live rect (never read by crop with nonzero weight).
// ---------------------------------------------------------------------------
__global__ __launch_bounds__(256) void resolve_kernel(const float* __restrict__ texture)
{
    int gid = blockIdx.x * 256 + threadIdx.x;
    int n = gid >> 14;                 // / (IMG*IMG)
    int pix = gid & (IMG * IMG - 1);
    int px = pix & (IMG - 1);
    int py = pix >> 7;
    int4 rect = g_rect[n];
    if (px < rect.x || px > rect.z || py < rect.y || py > rect.w) return;

    // merge partials: strict < keeps earliest split on exact depth ties,
    // matching sequential scan semantics (splits are index-ordered).
    const float2* part = g_part + (size_t)n * (IMG * IMG) + pix;
    float dmin = INFINITY;
    int w = -1;
#pragma unroll
    for (int s = 0; s < NSPLIT; s++) {
        float2 pr = part[(size_t)s * NR * IMG * IMG];
        if (pr.x < dmin) { dmin = pr.x; w = __float_as_int(pr.y); }
    }

    float gx = px + 0.5f;
    float gy = py + 0.5f;
    float u = 0.f, v = 0.f;
    float mask = 0.f;
    if (w >= 0) {
        mask = 1.f;
        const float4* trih = g_trih + (size_t)n * FMAX * 5;
        const float4* tric = g_tric + (size_t)n * FMAX * 3;
        float4 f0 = trih[w * 5 + 0];
        float4 f1 = trih[w * 5 + 1];
        float4 f2 = trih[w * 5 + 2];
        float4 c0 = tric[w * 3 + 0];
        float4 c1 = tric[w * 3 + 1];
        float4 c2 = tric[w * 3 + 2];
        float e0 = f0.x * (gy - f0.w) - f0.y * (gx - f0.z);
        float e1 = f1.x * (gy - f1.w) - f1.y * (gx - f1.z);
        float e2 = f2.x * (gy - f2.w) - f2.y * (gx - f2.z);
        float b0 = e0 * c0.x, b1 = e1 * c0.x, b2 = e2 * c0.x;
        float pw = b0 * c0.y + b1 * c0.z + b2 * c0.w;
        pw = (fabsf(pw) < 1e-12f) ? 1e-12f : pw;
        float ipw = 1.0f / pw;
        u = (b0 * c1.x + b1 * c1.y + b2 * c1.z) * ipw;
        v = (b0 * c2.x + b1 * c2.y + b2 * c2.z) * ipw;
    }

    // reference: idx = clip(uv[...,::-1],0,1) * [th,tw]  (row from v, col from u)
    int bidx = n & (NB - 1);
    const float* tex = texture + (size_t)bidx * THW * THW * TCH;
    float idy = fminf(fmaxf(v, 0.f), 1.f) * 1024.0f;
    float idx = fminf(fmaxf(u, 0.f), 1.f) * 1024.0f;
    float fly = floorf(idy), flx = floorf(idx);
    float fy = idy - fly, fx = idx - flx;
    int i = (int)fly, j = (int)flx;
    int i0 = min(max(i, 0), 1023), j0 = min(max(j, 0), 1023);
    int i1 = min(i + 1, 1023),     j1 = min(j + 1, 1023);
    const float4* t00 = (const float4*)(tex + ((size_t)i0 * 1024 + j0) * 8);
    const float4* t01 = (const float4*)(tex + ((size_t)i0 * 1024 + j1) * 8);
    const float4* t10 = (const float4*)(tex + ((size_t)i1 * 1024 + j0) * 8);
    const float4* t11 = (const float4*)(tex + ((size_t)i1 * 1024 + j1) * 8);
    float w00 = (1.f - fx) * (1.f - fy);
    float w01 = fx * (1.f - fy);
    float w10 = (1.f - fx) * fy;
    float w11 = fx * fy;
    float4 qa00 = t00[0], qb00 = t00[1];
    float4 qa01 = t01[0], qb01 = t01[1];
    float4 qa10 = t10[0], qb10 = t10[1];
    float4 qa11 = t11[0], qb11 = t11[1];
    float4 oa, ob;
    oa.x = qa00.x * w00 + qa01.x * w01 + qa10.x * w10 + qa11.x * w11;
    oa.y = qa00.y * w00 + qa01.y * w01 + qa10.y * w10 + qa11.y * w11;
    oa.z = qa00.z * w00 + qa01.z * w01 + qa10.z * w10 + qa11.z * w11;
    oa.w = qa00.w * w00 + qa01.w * w01 + qa10.w * w10 + qa11.w * w11;
    ob.x = qb00.x * w00 + qb01.x * w01 + qb10.x * w10 + qb11.x * w11;
    ob.y = qb00.y * w00 + qb01.y * w01 + qb10.y * w10 + qb11.y * w11;
    ob.z = qb00.z * w00 + qb01.z * w01 + qb10.z * w10 + qb11.z * w11;
    ob.w = qb00.w * w00 + qb01.w * w01 + qb10.w * w10 + qb11.w * w11;
    g_rend[(size_t)gid * 2 + 0] = oa;
    g_rend[(size_t)gid * 2 + 1] = ob;
    g_uvm[gid] = make_float4(u, v, mask, ((u + v) > 0.f) ? 1.f : 0.f);
}

// ---------------------------------------------------------------------------
// Kernel C: crop_and_resize (bilinear) + thresholds, one thread per out pixel
// ---------------------------------------------------------------------------
__global__ __launch_bounds__(256) void crop_kernel(const float* __restrict__ bboxes,
                                                   float* __restrict__ out)
{
    int gid = blockIdx.x * 256 + threadIdx.x;
    if (gid >= NR * TGT * TGT) return;
    int n = gid / (TGT * TGT);
    int pix = gid - n * (TGT * TGT);
    int ty = pix / TGT, tx = pix - (pix / TGT) * TGT;
    int b = n & 3, p = n >> 2;
    const float* bx = bboxes + (size_t)(b * NP + p) * 4;
    float y1 = bx[0], x1 = bx[1], y2 = bx[2], x2 = bx[3];
    float stepy = ((y2 - y1) * 127.0f) / 63.0f;
    float stepx = ((x2 - x1) * 127.0f) / 63.0f;
    float ys = y1 * 127.0f + (float)ty * stepy;
    float xs = x1 * 127.0f + (float)tx * stepx;
    bool vy = (ys >= 0.f) && (ys <= 127.f);
    bool vx = (xs >= 0.f) && (xs <= 127.f);
    bool valid = vy && vx;
    float yc = fminf(fmaxf(ys, 0.f), 127.f);
    float xc = fminf(fmaxf(xs, 0.f), 127.f);
    float y0f = floorf(yc), x0f = floorf(xc);
    float fy = yc - y0f, fx = xc - x0f;
    int i0 = (int)y0f, j0 = (int)x0f;
    int i1 = min(i0 + 1, 127), j1 = min(j0 + 1, 127);
    float w00 = (1.f - fy) * (1.f - fx);
    float w01 = (1.f - fy) * fx;
    float w10 = fy * (1.f - fx);
    float w11 = fy * fx;

    size_t ib = (size_t)n * (IMG * IMG);
    float4 m00 = g_uvm[ib + i0 * IMG + j0];
    float4 m01 = g_uvm[ib + i0 * IMG + j1];
    float4 m10 = g_uvm[ib + i1 * IMG + j0];
    float4 m11 = g_uvm[ib + i1 * IMG + j1];
    float4 ra00 = g_rend[(ib + i0 * IMG + j0) * 2],     rb00 = g_rend[(ib + i0 * IMG + j0) * 2 + 1];
    float4 ra01 = g_rend[(ib + i0 * IMG + j1) * 2],     rb01 = g_rend[(ib + i0 * IMG + j1) * 2 + 1];
    float4 ra10 = g_rend[(ib + i1 * IMG + j0) * 2],     rb10 = g_rend[(ib + i1 * IMG + j0) * 2 + 1];
    float4 ra11 = g_rend[(ib + i1 * IMG + j1) * 2],     rb11 = g_rend[(ib + i1 * IMG + j1) * 2 + 1];

    float mnew = m00.w * w00 + m01.w * w01 + m10.w * w10 + m11.w * w11;
    float mold = m00.z * w00 + m01.z * w01 + m10.z * w10 + m11.z * w11;
    float uo   = m00.x * w00 + m01.x * w01 + m10.x * w10 + m11.x * w11;
    float vo   = m00.y * w00 + m01.y * w01 + m10.y * w10 + m11.y * w11;
    float rc[8];
    rc[0] = ra00.x * w00 + ra01.x * w01 + ra10.x * w10 + ra11.x * w11;
    rc[1] = ra00.y * w00 + ra01.y * w01 + ra10.y * w10 + ra11.y * w11;
    rc[2] = ra00.z * w00 + ra01.z * w01 + ra10.z * w10 + ra11.z * w11;
    rc[3] = ra00.w * w00 + ra01.w * w01 + ra10.w * w10 + ra11.w * w11;
    rc[4] = rb00.x * w00 + rb01.x * w01 + rb10.x * w10 + rb11.x * w11;
    rc[5] = rb00.y * w00 + rb01.y * w01 + rb10.y * w10 + rb11.y * w11;
    rc[6] = rb00.z * w00 + rb01.z * w01 + rb10.z * w10 + rb11.z * w11;
    rc[7] = rb00.w * w00 + rb01.w * w01 + rb10.w * w10 + rb11.w * w11;

    float vscale = valid ? 1.0f : 0.0f;
    float4 o0, o1, o2;
    o0.x = (valid && mnew > 0.5f) ? 1.f : 0.f;
    o0.y = rc[0] * vscale;
    o0.z = rc[1] * vscale;
    o0.w = rc[2] * vscale;
    o1.x = rc[3] * vscale;
    o1.y = rc[4] * vscale;
    o1.z = rc[5] * vscale;
    o1.w = rc[6] * vscale;
    o2.x = rc[7] * vscale;
    o2.y = (valid && mold > 0.5f) ? 1.f : 0.f;
    o2.z = uo * vscale;
    o2.w = vo * vscale;
    float4* op = (float4*)(out + (size_t)gid * 12);
    op[0] = o0;
    op[1] = o1;
    op[2] = o2;
}

// ---------------------------------------------------------------------------
extern "C" void kernel_launch(void* const* d_in, const int* in_sizes, int n_in,
                              void* d_out, int out_size)
{
    const float* vertices = (const float*)d_in[0];
    const float* uv_map   = (const float*)d_in[1];
    const int*   faces    = (const int*)d_in[2];
    const float* texture  = (const float*)d_in[3];
    const float* poses    = (const float*)d_in[4];
    const float* bboxes   = (const float*)d_in[5];
    int V = in_sizes[0] / (NB * 3);
    int F = in_sizes[2] / (NB * 3);

    setup_kernel<<<NR, 256>>>(vertices, uv_map, faces, poses, bboxes, V, F);
    dim3 gB(16, NR, NSPLIT);
    raster_kernel<<<gB, 128>>>(F);
    int nfull = NR * IMG * IMG;
    resolve_kernel<<<nfull / 256, 256>>>(texture);
    int npix = NR * TGT * TGT;
    crop_kernel<<<(npix + 255) / 256, 256>>>(bboxes, (float*)d_out);
}

// round 9
// speedup vs baseline: 6.4581x; 1.2982x over previous
#include <cuda_runtime.h>
#include <math.h>

#define NB 4
#define NP 8
#define NR 32
#define IMG 128
#define THW 1024
#define TCH 8
#define TGT 64
#define VMAX 1024
#define FMAX 1024
#define NSPLIT 4

// Scratch (static device globals — no runtime allocation)
__device__ float4 g_vert[NR * VMAX];               // px, py, z, iw  (2.1 MB)
__device__ float  g_w[NR * VMAX];                  // clip w         (131 KB)
__device__ float4 g_trih[NR * FMAX * 5];           // hot: edges/bbox/z/zmin (6.5 MB)
__device__ float4 g_tric[NR * FMAX * 3];           // cold: ainv/iw/uw/vw (1.6 MB)
__device__ float2 g_part[NSPLIT * NR * IMG * IMG]; // 16.8 MB (depth, win) partials
__device__ float4 g_rend[NR * IMG * IMG * 2];      // 16.8 MB rendered 8ch
__device__ float4 g_uvm[NR * IMG * IMG];           // 8.4 MB (u, v, mask, mask_rend)
__device__ int4   g_rect[NR];                      // live pixel rect per render

// ---------------------------------------------------------------------------
// Kernel A1: vertex transform.  grid (NR, ceil(V/256)), block 256.
// ---------------------------------------------------------------------------
__global__ __launch_bounds__(256) void vertex_kernel(
    const float* __restrict__ vertices, const float* __restrict__ poses,
    const float* __restrict__ bboxes, int V)
{
    int n = blockIdx.x;
    int b = n & (NB - 1);
    int p = n >> 2;
    int v = blockIdx.y * 256 + threadIdx.x;

    if (blockIdx.y == 0 && threadIdx.x == 0) {
        // live rect: pixels crop can validly sample (padded ±1 vs ulp drift)
        const float* bx = bboxes + (size_t)(b * NP + p) * 4;
        float y1 = bx[0], x1 = bx[1], y2 = bx[2], x2 = bx[3];
        int ry0 = max(0, (int)floorf(fmaxf(0.f, y1 * 127.f)) - 1);
        int ry1 = min(127, (int)floorf(fminf(127.f, y2 * 127.f)) + 2);
        int rx0 = max(0, (int)floorf(fmaxf(0.f, x1 * 127.f)) - 1);
        int rx1 = min(127, (int)floorf(fminf(127.f, x2 * 127.f)) + 2);
        g_rect[n] = make_int4(rx0, ry0, rx1, ry1);
    }
    if (v >= V) return;

    const float* ps = poses + (size_t)(b * NP + p) * 16;
    // cam_pose row factors: rows 1,2 negated (gl), t sign folded the same way
    float r0 = ps[0],  r1 = ps[1],  r2 = ps[2],  r3 = ps[3];
    float r4 = -ps[4], r5 = -ps[5], r6 = -ps[6], r7 = -ps[7];
    float r8 = -ps[8], r9 = -ps[9], r10 = -ps[10], r11 = -ps[11];
    float r12 = ps[12], r13 = ps[13], r14 = ps[14], r15 = ps[15];

    const double ncd = 0.1, fcd = 10.0;
    const float Qf  = (float)(-(fcd + ncd) / (fcd - ncd));
    const float QNf = (float)(-2.0 * (fcd * ncd) / (fcd - ncd));
    const float S = 1.875f;  // 2*120/128

    const float* vp = vertices + ((size_t)b * V + v) * 3;
    float X = vp[0], Y = vp[1], Z = vp[2];
    float c0 = ((X * r0  + Y * r1)  + Z * r2)  + r3;
    float c1 = ((X * r4  + Y * r5)  + Z * r6)  + r7;
    float c2 = ((X * r8  + Y * r9)  + Z * r10) + r11;
    float c3 = ((X * r12 + Y * r13) + Z * r14) + r15;
    float clx = c0 * S;
    float cly = c1 * S;
    float clz = c2 * Qf + c3 * QNf;
    float w = -c2;
    float wsafe = (fabsf(w) < 1e-8f) ? 1e-8f : w;
    float ndx = clx / wsafe;
    float ndy = cly / wsafe;
    float ndz = clz / wsafe;
    float px = (ndx * 0.5f + 0.5f) * 128.0f;
    float py = (1.0f - (ndy * 0.5f + 0.5f)) * 128.0f;
    g_vert[(size_t)n * VMAX + v] = make_float4(px, py, ndz, 1.0f / wsafe);
    g_w[(size_t)n * VMAX + v] = w;
}

// ---------------------------------------------------------------------------
// Kernel A2: triangle setup.  grid (NR, ceil(F/256)), block 256.
// ---------------------------------------------------------------------------
__global__ __launch_bounds__(256) void face_kernel(
    const float* __restrict__ uv_map, const int* __restrict__ faces,
    int V, int F)
{
    int n = blockIdx.x;
    int b = n & (NB - 1);
    int f = blockIdx.y * 256 + threadIdx.x;
    if (f >= F) return;

    const float4* verts = g_vert + (size_t)n * VMAX;
    const float*  ws    = g_w    + (size_t)n * VMAX;
    const int* fp = faces + ((size_t)b * F + f) * 3;
    int i0 = fp[0], i1 = fp[1], i2 = fp[2];
    float4 A = verts[i0], Bv = verts[i1], C = verts[i2];
    bool front = (ws[i0] > 1e-8f) && (ws[i1] > 1e-8f) && (ws[i2] > 1e-8f);
    float area = (Bv.x - A.x) * (C.y - A.y) - (Bv.y - A.y) * (C.x - A.x);
    bool valid = front && (fabsf(area) > 1e-9f);
    float a_safe = (fabsf(area) < 1e-9f) ? 1.0f : area;
    float inva = 1.0f / a_safe;
    float s = (inva >= 0.0f) ? 1.0f : -1.0f;   // exact sign fold
    float ainv = fabsf(inva);
    // signed edge coefficients: e_i' = ex_i*(gy-ay_i) - ey_i*(gx-ax_i) = s*e_i
    float ex0 = s * (C.x - Bv.x),  ey0 = s * (C.y - Bv.y);   // edge(v1,v2), anchor v1
    float ex1 = s * (A.x - C.x),   ey1 = s * (A.y - C.y);    // edge(v2,v0), anchor v2
    float ex2 = s * (Bv.x - A.x),  ey2 = s * (Bv.y - A.y);   // edge(v0,v1), anchor v0
    float za = A.z * ainv, zb = Bv.z * ainv, zc = C.z * ainv;
    float zmin = fminf(A.z, fminf(Bv.z, C.z));               // early-z bound

    const float* uvb = uv_map + (size_t)b * V * 2;
    float u0 = uvb[i0 * 2], vv0 = uvb[i0 * 2 + 1];
    float u1 = uvb[i1 * 2], vv1 = uvb[i1 * 2 + 1];
    float u2 = uvb[i2 * 2], vv2 = uvb[i2 * 2 + 1];

    float bxmin, bymin, bxmax, bymax;
    if (valid) {
        bxmin = fminf(A.x, fminf(Bv.x, C.x)) - 0.5f;
        bxmax = fmaxf(A.x, fmaxf(Bv.x, C.x)) + 0.5f;
        bymin = fminf(A.y, fminf(Bv.y, C.y)) - 0.5f;
        bymax = fmaxf(A.y, fmaxf(Bv.y, C.y)) + 0.5f;
    } else {
        bxmin = 1e30f; bymin = 1e30f; bxmax = -1e30f; bymax = -1e30f;
    }
    float4* h = g_trih + ((size_t)n * FMAX + f) * 5;
    h[0] = make_float4(ex0, ey0, Bv.x, Bv.y);
    h[1] = make_float4(ex1, ey1, C.x, C.y);
    h[2] = make_float4(ex2, ey2, A.x, A.y);
    h[3] = make_float4(bxmin, bymin, bxmax, bymax);
    h[4] = make_float4(za, zb, zc, zmin);
    float4* c = g_tric + ((size_t)n * FMAX + f) * 3;
    c[0] = make_float4(ainv, A.w, Bv.w, C.w);
    c[1] = make_float4(A.w * u0, Bv.w * u1, C.w * u2, 0.0f);
    c[2] = make_float4(A.w * vv0, Bv.w * vv1, C.w * vv2, 0.0f);
}

// ---------------------------------------------------------------------------
// Kernel B: rasterize partials, restricted to the live rect, with warp-level
// early-z rejection.  Block = 128 cols x 8 rows. grid = (16, 32, NSPLIT)
// ---------------------------------------------------------------------------
__global__ __launch_bounds__(128) void raster_kernel(int F)
{
    __shared__ float4 s_tri[128 * 5];
    int n = blockIdx.y;
    int tile = blockIdx.x;
    int split = blockIdx.z;
    int r0 = tile * 8;
    int4 rect = g_rect[n];
    if (r0 > rect.w || r0 + 7 < rect.y) return;   // whole strip dead (uniform)

    int tid = threadIdx.x;            // column
    int lane = tid & 31;
    float gx = tid + 0.5f;
    float gy0 = r0 + 0.5f;
    int warp = tid >> 5;
    // warp rect clamped to live rect (warp-uniform)
    float wxmin = fmaxf(warp * 32 + 0.5f, rect.x + 0.5f);
    float wxmax = fminf(warp * 32 + 31.5f, rect.z + 0.5f);
    float rymin = fmaxf(r0 + 0.5f, rect.y + 0.5f);
    float rymax = fminf(r0 + 7.5f, rect.w + 0.5f);
    bool warp_live = (wxmin <= wxmax);

    float depth[8];
    int   win[8];
#pragma unroll
    for (int r = 0; r < 8; r++) { depth[r] = INFINITY; win[r] = -1; }

    int fbeg = (F * split) / NSPLIT;
    int fend = (F * (split + 1)) / NSPLIT;

    const float4* trih = g_trih + (size_t)n * FMAX * 5;
    for (int base = fbeg; base < fend; base += 128) {
        int cnt = min(128, fend - base);
        __syncthreads();
        for (int i = tid; i < cnt * 5; i += 128) s_tri[i] = trih[(size_t)base * 5 + i];
        __syncthreads();
        for (int t0 = 0; t0 < cnt; t0 += 32) {
            // Early-z bound: max surviving depth over this warp's pixels
            // (capped at far plane 1).  Stale-within-chunk => conservative.
            float lmax = depth[0];
#pragma unroll
            for (int r = 1; r < 8; r++) lmax = fmaxf(lmax, depth[r]);
#pragma unroll
            for (int off = 16; off > 0; off >>= 1)
                lmax = fmaxf(lmax, __shfl_xor_sync(0xffffffffu, lmax, off));
            float zbound = fminf(lmax, 1.0f) + 1e-4f;   // slack: reject-only-safe

            // lane L tests triangle t0+L: bbox vs warp rect, z-reject, then
            // exact edge-corner reject (max of each linear edge over rect).
            bool pass = false;
            int ti = t0 + lane;
            if (warp_live && ti < cnt) {
                float4 bb = s_tri[ti * 5 + 3];
                pass = !(bb.x > wxmax || bb.z < wxmin || bb.y > rymax || bb.w < rymin);
                if (pass) pass = (s_tri[ti * 5 + 4].w <= zbound);
                if (pass) {
                    float4 t0v = s_tri[ti * 5 + 0];
                    float4 t1v = s_tri[ti * 5 + 1];
                    float4 t2v = s_tri[ti * 5 + 2];
                    float y0s = (t0v.x >= 0.f) ? rymax : rymin;
                    float x0s = (t0v.y >= 0.f) ? wxmin : wxmax;
                    float em0 = t0v.x * (y0s - t0v.w) - t0v.y * (x0s - t0v.z);
                    float y1s = (t1v.x >= 0.f) ? rymax : rymin;
                    float x1s = (t1v.y >= 0.f) ? wxmin : wxmax;
                    float em1 = t1v.x * (y1s - t1v.w) - t1v.y * (x1s - t1v.z);
                    float y2s = (t2v.x >= 0.f) ? rymax : rymin;
                    float x2s = (t2v.y >= 0.f) ? wxmin : wxmax;
                    float em2 = t2v.x * (y2s - t2v.w) - t2v.y * (x2s - t2v.z);
                    pass = (em0 >= 0.f) && (em1 >= 0.f) && (em2 >= 0.f);
                }
            }
            unsigned mask = __ballot_sync(0xffffffffu, pass);
            while (mask) {
                int t = __ffs(mask) - 1;
                mask &= mask - 1;
                t += t0;
                float4 f0 = s_tri[t * 5 + 0];
                float4 f1 = s_tri[t * 5 + 1];
                float4 f2 = s_tri[t * 5 + 2];
                float4 f4 = s_tri[t * 5 + 4];
                // edges at (gx, gy0), anchored form
                float e0b = f0.x * (gy0 - f0.w) - f0.y * (gx - f0.z);
                float e1b = f1.x * (gy0 - f1.w) - f1.y * (gx - f1.z);
                float e2b = f2.x * (gy0 - f2.w) - f2.y * (gx - f2.z);
                float zpb = e0b * f4.x + e1b * f4.y + e2b * f4.z;
                float dzp = f0.x * f4.x + f1.x * f4.y + f2.x * f4.z;
                int tg = base + t;
#pragma unroll
                for (int r = 0; r < 8; r++) {
                    float rf = (float)r;
                    float e0 = fmaf(rf, f0.x, e0b);
                    float e1 = fmaf(rf, f1.x, e1b);
                    float e2 = fmaf(rf, f2.x, e2b);
                    float zp = fmaf(rf, dzp, zpb);
                    float m  = fminf(fminf(e0, e1), e2);
                    bool upd = (m >= 0.f) && (zp < depth[r]) && (fabsf(zp) <= 1.f);
                    depth[r] = upd ? zp : depth[r];
                    win[r]   = upd ? tg : win[r];
                }
            }
        }
    }

    float2* part = g_part + ((size_t)split * NR + n) * (IMG * IMG);
#pragma unroll
    for (int r = 0; r < 8; r++) {
        int y = r0 + r;
        part[y * IMG + tid] = make_float2(depth[r], __int_as_float(win[r]));
    }
}

// ---------------------------------------------------------------------------
// Kernel B2: merge split partials, resolve winner attrs, texture sample.
// Skips pixels outside the live rect (never read by crop with nonzero weight).
// ---------------------------------------------------------------------------
__global__ __launch_bounds__(256) void resolve_kernel(const float* __restrict__ texture)
{
    int gid = blockIdx.x * 256 + threadIdx.x;
    int n = gid >> 14;                 // / (IMG*IMG)
    int pix = gid & (IMG * IMG - 1);
    int px = pix & (IMG - 1);
    int py = pix >> 7;
    int4 rect = g_rect[n];
    if (px < rect.x || px > rect.z || py < rect.y || py > rect.w) return;

    // merge partials: strict < keeps earliest split on exact depth ties,
    // matching sequential scan semantics (splits are index-ordered).
    const float2* part = g_part + (size_t)n * (IMG * IMG) + pix;
    float dmin = INFINITY;
    int w = -1;
#pragma unroll
    for (int s = 0; s < NSPLIT; s++) {
        float2 pr = part[(size_t)s * NR * IMG * IMG];
        if (pr.x < dmin) { dmin = pr.x; w = __float_as_int(pr.y); }
    }

    float gx = px + 0.5f;
    float gy = py + 0.5f;
    float u = 0.f, v = 0.f;
    float mask = 0.f;
    if (w >= 0) {
        mask = 1.f;
        const float4* trih = g_trih + (size_t)n * FMAX * 5;
        const float4* tric = g_tric + (size_t)n * FMAX * 3;
        float4 f0 = trih[w * 5 + 0];
        float4 f1 = trih[w * 5 + 1];
        float4 f2 = trih[w * 5 + 2];
        float4 c0 = tric[w * 3 + 0];
        float4 c1 = tric[w * 3 + 1];
        float4 c2 = tric[w * 3 + 2];
        float e0 = f0.x * (gy - f0.w) - f0.y * (gx - f0.z);
        float e1 = f1.x * (gy - f1.w) - f1.y * (gx - f1.z);
        float e2 = f2.x * (gy - f2.w) - f2.y * (gx - f2.z);
        float b0 = e0 * c0.x, b1 = e1 * c0.x, b2 = e2 * c0.x;
        float pw = b0 * c0.y + b1 * c0.z + b2 * c0.w;
        pw = (fabsf(pw) < 1e-12f) ? 1e-12f : pw;
        float ipw = 1.0f / pw;
        u = (b0 * c1.x + b1 * c1.y + b2 * c1.z) * ipw;
        v = (b0 * c2.x + b1 * c2.y + b2 * c2.z) * ipw;
    }

    // reference: idx = clip(uv[...,::-1],0,1) * [th,tw]  (row from v, col from u)
    int bidx = n & (NB - 1);
    const float* tex = texture + (size_t)bidx * THW * THW * TCH;
    float idy = fminf(fmaxf(v, 0.f), 1.f) * 1024.0f;
    float idx = fminf(fmaxf(u, 0.f), 1.f) * 1024.0f;
    float fly = floorf(idy), flx = floorf(idx);
    float fy = idy - fly, fx = idx - flx;
    int i = (int)fly, j = (int)flx;
    int i0 = min(max(i, 0), 1023), j0 = min(max(j, 0), 1023);
    int i1 = min(i + 1, 1023),     j1 = min(j + 1, 1023);
    const float4* t00 = (const float4*)(tex + ((size_t)i0 * 1024 + j0) * 8);
    const float4* t01 = (const float4*)(tex + ((size_t)i0 * 1024 + j1) * 8);
    const float4* t10 = (const float4*)(tex + ((size_t)i1 * 1024 + j0) * 8);
    const float4* t11 = (const float4*)(tex + ((size_t)i1 * 1024 + j1) * 8);
    float w00 = (1.f - fx) * (1.f - fy);
    float w01 = fx * (1.f - fy);
    float w10 = (1.f - fx) * fy;
    float w11 = fx * fy;
    float4 qa00 = t00[0], qb00 = t00[1];
    float4 qa01 = t01[0], qb01 = t01[1];
    float4 qa10 = t10[0], qb10 = t10[1];
    float4 qa11 = t11[0], qb11 = t11[1];
    float4 oa, ob;
    oa.x = qa00.x * w00 + qa01.x * w01 + qa10.x * w10 + qa11.x * w11;
    oa.y = qa00.y * w00 + qa01.y * w01 + qa10.y * w10 + qa11.y * w11;
    oa.z = qa00.z * w00 + qa01.z * w01 + qa10.z * w10 + qa11.z * w11;
    oa.w = qa00.w * w00 + qa01.w * w01 + qa10.w * w10 + qa11.w * w11;
    ob.x = qb00.x * w00 + qb01.x * w01 + qb10.x * w10 + qb11.x * w11;
    ob.y = qb00.y * w00 + qb01.y * w01 + qb10.y * w10 + qb11.y * w11;
    ob.z = qb00.z * w00 + qb01.z * w01 + qb10.z * w10 + qb11.z * w11;
    ob.w = qb00.w * w00 + qb01.w * w01 + qb10.w * w10 + qb11.w * w11;
    g_rend[(size_t)gid * 2 + 0] = oa;
    g_rend[(size_t)gid * 2 + 1] = ob;
    g_uvm[gid] = make_float4(u, v, mask, ((u + v) > 0.f) ? 1.f : 0.f);
}

// ---------------------------------------------------------------------------
// Kernel C: crop_and_resize (bilinear) + thresholds, one thread per out pixel
// ---------------------------------------------------------------------------
__global__ __launch_bounds__(256) void crop_kernel(const float* __restrict__ bboxes,
                                                   float* __restrict__ out)
{
    int gid = blockIdx.x * 256 + threadIdx.x;
    if (gid >= NR * TGT * TGT) return;
    int n = gid / (TGT * TGT);
    int pix = gid - n * (TGT * TGT);
    int ty = pix / TGT, tx = pix - (pix / TGT) * TGT;
    int b = n & 3, p = n >> 2;
    const float* bx = bboxes + (size_t)(b * NP + p) * 4;
    float y1 = bx[0], x1 = bx[1], y2 = bx[2], x2 = bx[3];
    float stepy = ((y2 - y1) * 127.0f) / 63.0f;
    float stepx = ((x2 - x1) * 127.0f) / 63.0f;
    float ys = y1 * 127.0f + (float)ty * stepy;
    float xs = x1 * 127.0f + (float)tx * stepx;
    bool vy = (ys >= 0.f) && (ys <= 127.f);
    bool vx = (xs >= 0.f) && (xs <= 127.f);
    bool valid = vy && vx;
    float yc = fminf(fmaxf(ys, 0.f), 127.f);
    float xc = fminf(fmaxf(xs, 0.f), 127.f);
    float y0f = floorf(yc), x0f = floorf(xc);
    float fy = yc - y0f, fx = xc - x0f;
    int i0 = (int)y0f, j0 = (int)x0f;
    int i1 = min(i0 + 1, 127), j1 = min(j0 + 1, 127);
    float w00 = (1.f - fy) * (1.f - fx);
    float w01 = (1.f - fy) * fx;
    float w10 = fy * (1.f - fx);
    float w11 = fy * fx;

    size_t ib = (size_t)n * (IMG * IMG);
    float4 m00 = g_uvm[ib + i0 * IMG + j0];
    float4 m01 = g_uvm[ib + i0 * IMG + j1];
    float4 m10 = g_uvm[ib + i1 * IMG + j0];
    float4 m11 = g_uvm[ib + i1 * IMG + j1];
    float4 ra00 = g_rend[(ib + i0 * IMG + j0) * 2],     rb00 = g_rend[(ib + i0 * IMG + j0) * 2 + 1];
    float4 ra01 = g_rend[(ib + i0 * IMG + j1) * 2],     rb01 = g_rend[(ib + i0 * IMG + j1) * 2 + 1];
    float4 ra10 = g_rend[(ib + i1 * IMG + j0) * 2],     rb10 = g_rend[(ib + i1 * IMG + j0) * 2 + 1];
    float4 ra11 = g_rend[(ib + i1 * IMG + j1) * 2],     rb11 = g_rend[(ib + i1 * IMG + j1) * 2 + 1];

    float mnew = m00.w * w00 + m01.w * w01 + m10.w * w10 + m11.w * w11;
    float mold = m00.z * w00 + m01.z * w01 + m10.z * w10 + m11.z * w11;
    float uo   = m00.x * w00 + m01.x * w01 + m10.x * w10 + m11.x * w11;
    float vo   = m00.y * w00 + m01.y * w01 + m10.y * w10 + m11.y * w11;
    float rc[8];
    rc[0] = ra00.x * w00 + ra01.x * w01 + ra10.x * w10 + ra11.x * w11;
    rc[1] = ra00.y * w00 + ra01.y * w01 + ra10.y * w10 + ra11.y * w11;
    rc[2] = ra00.z * w00 + ra01.z * w01 + ra10.z * w10 + ra11.z * w11;
    rc[3] = ra00.w * w00 + ra01.w * w01 + ra10.w * w10 + ra11.w * w11;
    rc[4] = rb00.x * w00 + rb01.x * w01 + rb10.x * w10 + rb11.x * w11;
    rc[5] = rb00.y * w00 + rb01.y * w01 + rb10.y * w10 + rb11.y * w11;
    rc[6] = rb00.z * w00 + rb01.z * w01 + rb10.z * w10 + rb11.z * w11;
    rc[7] = rb00.w * w00 + rb01.w * w01 + rb10.w * w10 + rb11.w * w11;

    float vscale = valid ? 1.0f : 0.0f;
    float4 o0, o1, o2;
    o0.x = (valid && mnew > 0.5f) ? 1.f : 0.f;
    o0.y = rc[0] * vscale;
    o0.z = rc[1] * vscale;
    o0.w = rc[2] * vscale;
    o1.x = rc[3] * vscale;
    o1.y = rc[4] * vscale;
    o1.z = rc[5] * vscale;
    o1.w = rc[6] * vscale;
    o2.x = rc[7] * vscale;
    o2.y = (valid && mold > 0.5f) ? 1.f : 0.f;
    o2.z = uo * vscale;
    o2.w = vo * vscale;
    float4* op = (float4*)(out + (size_t)gid * 12);
    op[0] = o0;
    op[1] = o1;
    op[2] = o2;
}

// ---------------------------------------------------------------------------
extern "C" void kernel_launch(void* const* d_in, const int* in_sizes, int n_in,
                              void* d_out, int out_size)
{
    const float* vertices = (const float*)d_in[0];
    const float* uv_map   = (const float*)d_in[1];
    const int*   faces    = (const int*)d_in[2];
    const float* texture  = (const float*)d_in[3];
    const float* poses    = (const float*)d_in[4];
    const float* bboxes   = (const float*)d_in[5];
    int V = in_sizes[0] / (NB * 3);
    int F = in_sizes[2] / (NB * 3);

    dim3 gV(NR, (V + 255) / 256);
    vertex_kernel<<<gV, 256>>>(vertices, poses, bboxes, V);
    dim3 gF(NR, (F + 255) / 256);
    face_kernel<<<gF, 256>>>(uv_map, faces, V, F);
    dim3 gB(16, NR, NSPLIT);
    raster_kernel<<<gB, 128>>>(F);
    int nfull = NR * IMG * IMG;
    resolve_kernel<<<nfull / 256, 256>>>(texture);
    int npix = NR * TGT * TGT;
    crop_kernel<<<(npix + 255) / 256, 256>>>(bboxes, (float*)d_out);
}